// round 7
// baseline (speedup 1.0000x reference)
#include <cuda_runtime.h>
#include <cuda_bf16.h>
#include <math.h>

// Problem constants
#define T 256
#define HD 1024
#define ID 768
#define NE 32
#define TK 6
#define NG 8
#define GSZ 4   // experts per group
#define KG 4    // top-k groups

#define BM 64
#define BK 32
#define LSTR (BK + 4)   // 36 floats: fragment LDS conflict-free, float4-aligned rows

// ---------------- scratch ----------------
__device__ int   g_cnt[NE];
__device__ int   g_tok[NE * T];
__device__ int   g_slot[NE * T];
__device__ float g_wt[T * TK];
__device__ float g_act[(size_t)NE * T * ID];   // [e][m][i]
__device__ float g_y[(size_t)T * TK * HD];     // [t][k][h]

// ---------------- routing ----------------
__global__ void routing_kernel(const float* __restrict__ logits,
                               const float* __restrict__ bias) {
    int tid = threadIdx.x;
    if (tid < NE) g_cnt[tid] = 0;
    __syncthreads();

    int t = tid;
    float s[NE], sc[NE];
#pragma unroll
    for (int e = 0; e < NE; e++) {
        float l = logits[t * NE + e];
        float sig = 1.0f / (1.0f + expf(-l));
        s[e] = sig;
        sc[e] = sig + bias[e];
    }
    float gs[NG];
#pragma unroll
    for (int g = 0; g < NG; g++) {
        float m1 = -3.4e38f, m2 = -3.4e38f;
#pragma unroll
        for (int j = 0; j < GSZ; j++) {
            float v = sc[g * GSZ + j];
            if (v > m1) { m2 = m1; m1 = v; }
            else if (v > m2) { m2 = v; }
        }
        gs[g] = m1 + m2;
    }
    bool gsel[NG];
#pragma unroll
    for (int g = 0; g < NG; g++) gsel[g] = false;
#pragma unroll
    for (int it = 0; it < KG; it++) {
        float best = -3.4e38f; int bi = 0;
#pragma unroll
        for (int g = 0; g < NG; g++)
            if (!gsel[g] && gs[g] > best) { best = gs[g]; bi = g; }
        gsel[bi] = true;
    }
    float msc[NE];
#pragma unroll
    for (int e = 0; e < NE; e++)
        msc[e] = gsel[e / GSZ] ? sc[e] : -3.4e38f;

    int ids[TK]; float w[TK]; float wsum = 0.0f;
#pragma unroll
    for (int k = 0; k < TK; k++) {
        float best = -3.4e38f; int bi = 0;
#pragma unroll
        for (int e = 0; e < NE; e++)
            if (msc[e] > best) { best = msc[e]; bi = e; }
        ids[k] = bi;
        msc[bi] = -3.4e38f;
        w[k] = s[bi];
        wsum += w[k];
    }
    float inv = 1.0f / wsum;
#pragma unroll
    for (int k = 0; k < TK; k++) {
        g_wt[t * TK + k] = w[k] * inv;
        int e = ids[k];
        int j = atomicAdd(&g_cnt[e], 1);
        g_tok[e * T + j]  = t;
        g_slot[e * T + j] = k;
    }
}

// ---------------- tf32 mma helpers ----------------
__device__ __forceinline__ void mma8(float* c, const unsigned* a, const unsigned* b) {
    asm volatile(
        "mma.sync.aligned.m16n8k8.row.col.f32.tf32.tf32.f32 "
        "{%0,%1,%2,%3}, {%4,%5,%6,%7}, {%8,%9}, {%0,%1,%2,%3};\n"
        : "+f"(c[0]), "+f"(c[1]), "+f"(c[2]), "+f"(c[3])
        : "r"(a[0]), "r"(a[1]), "r"(a[2]), "r"(a[3]), "r"(b[0]), "r"(b[1]));
}
// 3xTF32 split: hi = top 19 bits (exactly representable in tf32), lo = residual
__device__ __forceinline__ void split2(float v, unsigned& hi, unsigned& lo) {
    unsigned h = __float_as_uint(v) & 0xFFFFE000u;
    hi = h;
    lo = __float_as_uint(v - __uint_as_float(h));
}

// ---------------- GEMM1 + SiLU (tensor core, 3xTF32) ----------------
// act[e][m][i] = silu(h[m]·w13g[i]) * (h[m]·w13u[i])
// block: 64(m) x 64(i), 8 warps (4m x 2n), each warp m16 x n32 (gate & up)
__global__ __launch_bounds__(256) void gemm1_kernel(const float* __restrict__ hidden,
                                                    const float* __restrict__ w13) {
    int e = blockIdx.z;
    int cnt = g_cnt[e];
    int m0 = blockIdx.y * BM;
    if (m0 >= cnt) return;
    int i0 = blockIdx.x * 64;

    __shared__ float As[BM][LSTR];
    __shared__ float Bg[64][LSTR];
    __shared__ float Bu[64][LSTR];
    __shared__ int toks[BM];

    int tid = threadIdx.x;
    int lane = tid & 31, wid = tid >> 5;
    int wm = wid & 3, wn = wid >> 2;
    int gid = lane >> 2, tg = lane & 3;

    if (tid < BM) toks[tid] = (m0 + tid < cnt) ? g_tok[e * T + m0 + tid] : -1;
    __syncthreads();

    const float* w13e = w13 + (size_t)e * 2 * ID * HD;

    float cg[4][4], cu[4][4];
#pragma unroll
    for (int j = 0; j < 4; j++)
#pragma unroll
        for (int q = 0; q < 4; q++) { cg[j][q] = 0.f; cu[j][q] = 0.f; }

    int lr = tid >> 3;        // 0..31 (2 row passes)
    int lc = (tid & 7) * 4;   // 0..28

    for (int k0 = 0; k0 < HD; k0 += BK) {
#pragma unroll
        for (int rr = 0; rr < 2; rr++) {
            int row = lr + rr * 32;
            int tok = toks[row];
            float4 v = (tok >= 0)
                ? *(const float4*)(hidden + (size_t)tok * HD + k0 + lc)
                : make_float4(0.f, 0.f, 0.f, 0.f);
            *(float4*)&As[row][lc] = v;
            *(float4*)&Bg[row][lc] = *(const float4*)(w13e + (size_t)(i0 + row) * HD + k0 + lc);
            *(float4*)&Bu[row][lc] = *(const float4*)(w13e + (size_t)(ID + i0 + row) * HD + k0 + lc);
        }
        __syncthreads();

#pragma unroll
        for (int kk = 0; kk < BK; kk += 8) {
            unsigned ah[4], al[4];
            int mrow = wm * 16 + gid;
            split2(As[mrow][kk + tg],         ah[0], al[0]);
            split2(As[mrow + 8][kk + tg],     ah[1], al[1]);
            split2(As[mrow][kk + tg + 4],     ah[2], al[2]);
            split2(As[mrow + 8][kk + tg + 4], ah[3], al[3]);
#pragma unroll
            for (int j = 0; j < 4; j++) {
                int nrow = wn * 32 + j * 8 + gid;
                unsigned bh[2], bl[2];
                split2(Bg[nrow][kk + tg],     bh[0], bl[0]);
                split2(Bg[nrow][kk + tg + 4], bh[1], bl[1]);
                mma8(cg[j], al, bh); mma8(cg[j], ah, bl); mma8(cg[j], ah, bh);
                split2(Bu[nrow][kk + tg],     bh[0], bl[0]);
                split2(Bu[nrow][kk + tg + 4], bh[1], bl[1]);
                mma8(cu[j], al, bh); mma8(cu[j], ah, bl); mma8(cu[j], ah, bh);
            }
        }
        __syncthreads();
    }

#pragma unroll
    for (int j = 0; j < 4; j++) {
        int col = i0 + wn * 32 + j * 8 + tg * 2;
#pragma unroll
        for (int half = 0; half < 2; half++) {
            int m = m0 + wm * 16 + gid + half * 8;
            if (m < cnt) {
                float g0 = cg[j][half * 2], g1 = cg[j][half * 2 + 1];
                float u0 = cu[j][half * 2], u1 = cu[j][half * 2 + 1];
                float a0 = g0 / (1.f + expf(-g0)) * u0;
                float a1 = g1 / (1.f + expf(-g1)) * u1;
                *(float2*)(g_act + ((size_t)(e * T + m)) * ID + col) = make_float2(a0, a1);
            }
        }
    }
}

// ---------------- GEMM2 (tensor core, 3xTF32) ----------------
// y[t][slot][h] = act[e][m]·w2[e][h]
__global__ __launch_bounds__(256) void gemm2_kernel(const float* __restrict__ w2) {
    int e = blockIdx.z;
    int cnt = g_cnt[e];
    int m0 = blockIdx.y * BM;
    if (m0 >= cnt) return;
    int h0 = blockIdx.x * 64;

    __shared__ float As[BM][LSTR];
    __shared__ float Bs[64][LSTR];

    int tid = threadIdx.x;
    int lane = tid & 31, wid = tid >> 5;
    int wm = wid & 3, wn = wid >> 2;
    int gid = lane >> 2, tg = lane & 3;

    const float* w2e = w2 + (size_t)e * HD * ID;
    const float* acte = g_act + (size_t)e * T * ID;

    float acc[4][4];
#pragma unroll
    for (int j = 0; j < 4; j++)
#pragma unroll
        for (int q = 0; q < 4; q++) acc[j][q] = 0.f;

    int lr = tid >> 3;
    int lc = (tid & 7) * 4;

    for (int k0 = 0; k0 < ID; k0 += BK) {
#pragma unroll
        for (int rr = 0; rr < 2; rr++) {
            int row = lr + rr * 32;
            float4 v = (m0 + row < cnt)
                ? *(const float4*)(acte + (size_t)(m0 + row) * ID + k0 + lc)
                : make_float4(0.f, 0.f, 0.f, 0.f);
            *(float4*)&As[row][lc] = v;
            *(float4*)&Bs[row][lc] = *(const float4*)(w2e + (size_t)(h0 + row) * ID + k0 + lc);
        }
        __syncthreads();

#pragma unroll
        for (int kk = 0; kk < BK; kk += 8) {
            unsigned ah[4], al[4];
            int mrow = wm * 16 + gid;
            split2(As[mrow][kk + tg],         ah[0], al[0]);
            split2(As[mrow + 8][kk + tg],     ah[1], al[1]);
            split2(As[mrow][kk + tg + 4],     ah[2], al[2]);
            split2(As[mrow + 8][kk + tg + 4], ah[3], al[3]);
#pragma unroll
            for (int j = 0; j < 4; j++) {
                int nrow = wn * 32 + j * 8 + gid;
                unsigned bh[2], bl[2];
                split2(Bs[nrow][kk + tg],     bh[0], bl[0]);
                split2(Bs[nrow][kk + tg + 4], bh[1], bl[1]);
                mma8(acc[j], al, bh); mma8(acc[j], ah, bl); mma8(acc[j], ah, bh);
            }
        }
        __syncthreads();
    }

    // epilogue: per-row token/slot lookup, store to y
    int mA = m0 + wm * 16 + gid;
    int mB = mA + 8;
    int tA = 0, sA = 0, tB = 0, sB = 0;
    if (mA < cnt) { tA = g_tok[e * T + mA]; sA = g_slot[e * T + mA]; }
    if (mB < cnt) { tB = g_tok[e * T + mB]; sB = g_slot[e * T + mB]; }
#pragma unroll
    for (int j = 0; j < 4; j++) {
        int col = h0 + wn * 32 + j * 8 + tg * 2;
        if (mA < cnt)
            *(float2*)(g_y + ((size_t)(tA * TK + sA)) * HD + col)
                = make_float2(acc[j][0], acc[j][1]);
        if (mB < cnt)
            *(float2*)(g_y + ((size_t)(tB * TK + sB)) * HD + col)
                = make_float2(acc[j][2], acc[j][3]);
    }
}

// ---------------- combine ----------------
__global__ void combine_kernel(float* __restrict__ out) {
    int idx = blockIdx.x * blockDim.x + threadIdx.x;
    int t = idx / (HD / 4);
    int h4 = (idx % (HD / 4)) * 4;
    float4 o = make_float4(0.f, 0.f, 0.f, 0.f);
#pragma unroll
    for (int k = 0; k < TK; k++) {
        float w = g_wt[t * TK + k];
        float4 yv = *(const float4*)(g_y + ((size_t)(t * TK + k)) * HD + h4);
        o.x += w * yv.x; o.y += w * yv.y; o.z += w * yv.z; o.w += w * yv.w;
    }
    *(float4*)(out + (size_t)t * HD + h4) = o;
}

// ---------------- launcher ----------------
extern "C" void kernel_launch(void* const* d_in, const int* in_sizes, int n_in,
                              void* d_out, int out_size) {
    const float* hidden = (const float*)d_in[0];
    const float* logits = (const float*)d_in[1];
    const float* bias   = (const float*)d_in[2];
    const float* w13    = (const float*)d_in[3];
    const float* w2     = (const float*)d_in[4];
    float* out = (float*)d_out;

    routing_kernel<<<1, 256>>>(logits, bias);

    dim3 g1(ID / 64, T / BM, NE);   // 12 x 4 x 32
    gemm1_kernel<<<g1, 256>>>(hidden, w13);

    dim3 g2(HD / 64, T / BM, NE);   // 16 x 4 x 32
    gemm2_kernel<<<g2, 256>>>(w2);

    combine_kernel<<<(T * HD / 4) / 256, 256>>>(out);
}

// round 8
// speedup vs baseline: 1.1014x; 1.1014x over previous
#include <cuda_runtime.h>
#include <cuda_bf16.h>
#include <math.h>
#include <stdint.h>

#define T 256
#define HD 1024
#define ID 768
#define NE 32
#define TK 6
#define NG 8
#define GSZ 4
#define KG 4

#define STR 36           // smem row stride in floats (k32 + pad, conflict-free, 16B-aligned)
#define TILE_F (320 * STR)   // gemm1 per-buffer floats: (64 A + 128 Bg + 128 Bu) * 36 = 11520
// gemm2 per-buffer: (64 A + 256 B) * 36 = 11520  (same size)

// ---------------- scratch ----------------
__device__ int   g_cnt[NE];
__device__ int   g_tok[NE * T];
__device__ int   g_slot[NE * T];
__device__ float g_wt[T * TK];
__device__ float g_act[(size_t)NE * T * ID];
__device__ float g_y[(size_t)T * TK * HD];

// ---------------- routing (unchanged, verified) ----------------
__global__ void routing_kernel(const float* __restrict__ logits,
                               const float* __restrict__ bias) {
    int tid = threadIdx.x;
    if (tid < NE) g_cnt[tid] = 0;
    __syncthreads();

    int t = tid;
    float s[NE], sc[NE];
#pragma unroll
    for (int e = 0; e < NE; e++) {
        float l = logits[t * NE + e];
        float sig = 1.0f / (1.0f + expf(-l));
        s[e] = sig;
        sc[e] = sig + bias[e];
    }
    float gs[NG];
#pragma unroll
    for (int g = 0; g < NG; g++) {
        float m1 = -3.4e38f, m2 = -3.4e38f;
#pragma unroll
        for (int j = 0; j < GSZ; j++) {
            float v = sc[g * GSZ + j];
            if (v > m1) { m2 = m1; m1 = v; }
            else if (v > m2) { m2 = v; }
        }
        gs[g] = m1 + m2;
    }
    bool gsel[NG];
#pragma unroll
    for (int g = 0; g < NG; g++) gsel[g] = false;
#pragma unroll
    for (int it = 0; it < KG; it++) {
        float best = -3.4e38f; int bi = 0;
#pragma unroll
        for (int g = 0; g < NG; g++)
            if (!gsel[g] && gs[g] > best) { best = gs[g]; bi = g; }
        gsel[bi] = true;
    }
    float msc[NE];
#pragma unroll
    for (int e = 0; e < NE; e++)
        msc[e] = gsel[e / GSZ] ? sc[e] : -3.4e38f;

    int ids[TK]; float w[TK]; float wsum = 0.0f;
#pragma unroll
    for (int k = 0; k < TK; k++) {
        float best = -3.4e38f; int bi = 0;
#pragma unroll
        for (int e = 0; e < NE; e++)
            if (msc[e] > best) { best = msc[e]; bi = e; }
        ids[k] = bi;
        msc[bi] = -3.4e38f;
        w[k] = s[bi];
        wsum += w[k];
    }
    float inv = 1.0f / wsum;
#pragma unroll
    for (int k = 0; k < TK; k++) {
        g_wt[t * TK + k] = w[k] * inv;
        int e = ids[k];
        int j = atomicAdd(&g_cnt[e], 1);
        g_tok[e * T + j]  = t;
        g_slot[e * T + j] = k;
    }
}

// ---------------- helpers ----------------
__device__ __forceinline__ void mma8(float* c, const unsigned* a, const unsigned* b) {
    asm volatile(
        "mma.sync.aligned.m16n8k8.row.col.f32.tf32.tf32.f32 "
        "{%0,%1,%2,%3}, {%4,%5,%6,%7}, {%8,%9}, {%0,%1,%2,%3};\n"
        : "+f"(c[0]), "+f"(c[1]), "+f"(c[2]), "+f"(c[3])
        : "r"(a[0]), "r"(a[1]), "r"(a[2]), "r"(a[3]), "r"(b[0]), "r"(b[1]));
}
__device__ __forceinline__ void split2(float v, unsigned& hi, unsigned& lo) {
    unsigned h = __float_as_uint(v) & 0xFFFFE000u;
    hi = h;
    lo = __float_as_uint(v - __uint_as_float(h));
}
__device__ __forceinline__ uint32_t s2u(const void* p) {
    return (uint32_t)__cvta_generic_to_shared(p);
}
__device__ __forceinline__ void cpa16(uint32_t dst, const void* src, int sz) {
    asm volatile("cp.async.cg.shared.global [%0], [%1], 16, %2;\n"
                 :: "r"(dst), "l"(src), "r"(sz));
}
__device__ __forceinline__ void cpa_commit() {
    asm volatile("cp.async.commit_group;\n");
}
__device__ __forceinline__ void cpa_wait1() {
    asm volatile("cp.async.wait_group 1;\n");
}
__device__ __forceinline__ void cpa_wait0() {
    asm volatile("cp.async.wait_group 0;\n");
}

// ---------------- GEMM1 + SiLU ----------------
// block: m64 x i128 (gate & up). 8 warps: wm=wid&1 (m32), wi=wid>>1 (i32).
// smem/buffer: A[64][36] | Bg[128][36] | Bu[128][36], double buffered.
#define G1_A  0
#define G1_BG (64 * STR)
#define G1_BU ((64 + 128) * STR)

__global__ __launch_bounds__(256, 2) void gemm1_kernel(const float* __restrict__ hidden,
                                                       const float* __restrict__ w13) {
    int e = blockIdx.z;
    int cnt = g_cnt[e];
    int m0 = blockIdx.y * 64;
    if (m0 >= cnt) return;
    int i0 = blockIdx.x * 128;

    extern __shared__ __align__(16) float smem[];
    float* bufs[2] = { smem, smem + TILE_F };

    int tid = threadIdx.x;
    int lane = tid & 31, wid = tid >> 5;
    int wm = wid & 1, wi = wid >> 1;
    int gid = lane >> 2, tg = lane & 3;

    const float* w13e = w13 + (size_t)e * 2 * ID * HD;

    // loader row/token precompute (rows tid>>3 and +32 for A)
    int arow0 = tid >> 3;
    int arow1 = arow0 + 32;
    int akp = (tid & 7) * 4;
    int tokA0 = (m0 + arow0 < cnt) ? g_tok[e * T + m0 + arow0] : -1;
    int tokA1 = (m0 + arow1 < cnt) ? g_tok[e * T + m0 + arow1] : -1;

    float cg[2][4][4], cu[2][4][4];
#pragma unroll
    for (int f = 0; f < 2; f++)
#pragma unroll
        for (int j = 0; j < 4; j++)
#pragma unroll
            for (int q = 0; q < 4; q++) { cg[f][j][q] = 0.f; cu[f][j][q] = 0.f; }

    // ---- loader lambda (macro-style) ----
#define G1_LOAD(buf, k0)                                                              \
    {                                                                                 \
        float* b_ = (buf);                                                            \
        cpa16(s2u(b_ + G1_A + arow0 * STR + akp),                                     \
              hidden + (size_t)(tokA0 < 0 ? 0 : tokA0) * HD + (k0) + akp,             \
              tokA0 >= 0 ? 16 : 0);                                                   \
        cpa16(s2u(b_ + G1_A + arow1 * STR + akp),                                     \
              hidden + (size_t)(tokA1 < 0 ? 0 : tokA1) * HD + (k0) + akp,             \
              tokA1 >= 0 ? 16 : 0);                                                   \
        _Pragma("unroll")                                                             \
        for (int j_ = 0; j_ < 4; j_++) {                                              \
            int idx_ = tid + 256 * j_;                                                \
            int row_ = idx_ >> 3;                                                     \
            int kp_ = (idx_ & 7) * 4;                                                 \
            cpa16(s2u(b_ + G1_BG + row_ * STR + kp_),                                 \
                  w13e + (size_t)(i0 + row_) * HD + (k0) + kp_, 16);                  \
            cpa16(s2u(b_ + G1_BU + row_ * STR + kp_),                                 \
                  w13e + (size_t)(ID + i0 + row_) * HD + (k0) + kp_, 16);             \
        }                                                                             \
        cpa_commit();                                                                 \
    }

    G1_LOAD(bufs[0], 0);

    const int NT = HD / 32;   // 32
    for (int kt = 0; kt < NT; kt++) {
        float* cur = bufs[kt & 1];
        if (kt + 1 < NT) {
            G1_LOAD(bufs[(kt + 1) & 1], (kt + 1) * 32);
            cpa_wait1();
        } else {
            cpa_wait0();
        }
        __syncthreads();

#pragma unroll
        for (int kk = 0; kk < 32; kk += 8) {
            unsigned ah[2][4], al[2][4];
#pragma unroll
            for (int f = 0; f < 2; f++) {
                int rb = wm * 32 + f * 16;
                split2(cur[G1_A + (rb + gid) * STR + kk + tg],         ah[f][0], al[f][0]);
                split2(cur[G1_A + (rb + gid + 8) * STR + kk + tg],     ah[f][1], al[f][1]);
                split2(cur[G1_A + (rb + gid) * STR + kk + tg + 4],     ah[f][2], al[f][2]);
                split2(cur[G1_A + (rb + gid + 8) * STR + kk + tg + 4], ah[f][3], al[f][3]);
            }
#pragma unroll
            for (int j = 0; j < 4; j++) {
                int nr = wi * 32 + j * 8 + gid;
                unsigned bh[2], bl[2];
                split2(cur[G1_BG + nr * STR + kk + tg],     bh[0], bl[0]);
                split2(cur[G1_BG + nr * STR + kk + tg + 4], bh[1], bl[1]);
#pragma unroll
                for (int f = 0; f < 2; f++) {
                    mma8(cg[f][j], al[f], bh);
                    mma8(cg[f][j], ah[f], bl);
                    mma8(cg[f][j], ah[f], bh);
                }
                split2(cur[G1_BU + nr * STR + kk + tg],     bh[0], bl[0]);
                split2(cur[G1_BU + nr * STR + kk + tg + 4], bh[1], bl[1]);
#pragma unroll
                for (int f = 0; f < 2; f++) {
                    mma8(cu[f][j], al[f], bh);
                    mma8(cu[f][j], ah[f], bl);
                    mma8(cu[f][j], ah[f], bh);
                }
            }
        }
        __syncthreads();
    }

    // epilogue
#pragma unroll
    for (int f = 0; f < 2; f++) {
        int r0 = m0 + wm * 32 + f * 16 + gid;
        int r1 = r0 + 8;
#pragma unroll
        for (int j = 0; j < 4; j++) {
            int col = i0 + wi * 32 + j * 8 + tg * 2;
            if (r0 < cnt) {
                float g0 = cg[f][j][0], g1 = cg[f][j][1];
                float u0 = cu[f][j][0], u1 = cu[f][j][1];
                *(float2*)(g_act + ((size_t)(e * T + r0)) * ID + col)
                    = make_float2(g0 / (1.f + expf(-g0)) * u0,
                                  g1 / (1.f + expf(-g1)) * u1);
            }
            if (r1 < cnt) {
                float g2 = cg[f][j][2], g3 = cg[f][j][3];
                float u2 = cu[f][j][2], u3 = cu[f][j][3];
                *(float2*)(g_act + ((size_t)(e * T + r1)) * ID + col)
                    = make_float2(g2 / (1.f + expf(-g2)) * u2,
                                  g3 / (1.f + expf(-g3)) * u3);
            }
        }
    }
#undef G1_LOAD
}

// ---------------- GEMM2 ----------------
// block: m64 x h256. 8 warps: wm=wid&1 (m32), wh=wid>>1 (h64).
// smem/buffer: A[64][36] | B[256][36], double buffered (same TILE_F).
#define G2_A 0
#define G2_B (64 * STR)

__global__ __launch_bounds__(256, 2) void gemm2_kernel(const float* __restrict__ w2) {
    int e = blockIdx.z;
    int cnt = g_cnt[e];
    int m0 = blockIdx.y * 64;
    if (m0 >= cnt) return;
    int h0 = blockIdx.x * 256;

    extern __shared__ __align__(16) float smem[];
    float* bufs[2] = { smem, smem + TILE_F };

    int tid = threadIdx.x;
    int lane = tid & 31, wid = tid >> 5;
    int wm = wid & 1, wh = wid >> 1;
    int gid = lane >> 2, tg = lane & 3;

    const float* w2e = w2 + (size_t)e * HD * ID;
    const float* acte = g_act + (size_t)e * T * ID;

    int arow0 = tid >> 3;
    int arow1 = arow0 + 32;
    int akp = (tid & 7) * 4;
    int pA0 = (m0 + arow0 < cnt) ? 16 : 0;
    int pA1 = (m0 + arow1 < cnt) ? 16 : 0;

    float acc[2][8][4];
#pragma unroll
    for (int f = 0; f < 2; f++)
#pragma unroll
        for (int j = 0; j < 8; j++)
#pragma unroll
            for (int q = 0; q < 4; q++) acc[f][j][q] = 0.f;

#define G2_LOAD(buf, k0)                                                              \
    {                                                                                 \
        float* b_ = (buf);                                                            \
        cpa16(s2u(b_ + G2_A + arow0 * STR + akp),                                     \
              acte + (size_t)(m0 + arow0) * ID + (k0) + akp, pA0);                    \
        cpa16(s2u(b_ + G2_A + arow1 * STR + akp),                                     \
              acte + (size_t)(m0 + arow1) * ID + (k0) + akp, pA1);                    \
        _Pragma("unroll")                                                             \
        for (int j_ = 0; j_ < 8; j_++) {                                              \
            int idx_ = tid + 256 * j_;                                                \
            int row_ = idx_ >> 3;                                                     \
            int kp_ = (idx_ & 7) * 4;                                                 \
            cpa16(s2u(b_ + G2_B + row_ * STR + kp_),                                  \
                  w2e + (size_t)(h0 + row_) * ID + (k0) + kp_, 16);                   \
        }                                                                             \
        cpa_commit();                                                                 \
    }

    G2_LOAD(bufs[0], 0);

    const int NT = ID / 32;   // 24
    for (int kt = 0; kt < NT; kt++) {
        float* cur = bufs[kt & 1];
        if (kt + 1 < NT) {
            G2_LOAD(bufs[(kt + 1) & 1], (kt + 1) * 32);
            cpa_wait1();
        } else {
            cpa_wait0();
        }
        __syncthreads();

#pragma unroll
        for (int kk = 0; kk < 32; kk += 8) {
            unsigned ah[2][4], al[2][4];
#pragma unroll
            for (int f = 0; f < 2; f++) {
                int rb = wm * 32 + f * 16;
                split2(cur[G2_A + (rb + gid) * STR + kk + tg],         ah[f][0], al[f][0]);
                split2(cur[G2_A + (rb + gid + 8) * STR + kk + tg],     ah[f][1], al[f][1]);
                split2(cur[G2_A + (rb + gid) * STR + kk + tg + 4],     ah[f][2], al[f][2]);
                split2(cur[G2_A + (rb + gid + 8) * STR + kk + tg + 4], ah[f][3], al[f][3]);
            }
#pragma unroll
            for (int j = 0; j < 8; j++) {
                int nr = wh * 64 + j * 8 + gid;
                unsigned bh[2], bl[2];
                split2(cur[G2_B + nr * STR + kk + tg],     bh[0], bl[0]);
                split2(cur[G2_B + nr * STR + kk + tg + 4], bh[1], bl[1]);
#pragma unroll
                for (int f = 0; f < 2; f++) {
                    mma8(acc[f][j], al[f], bh);
                    mma8(acc[f][j], ah[f], bl);
                    mma8(acc[f][j], ah[f], bh);
                }
            }
        }
        __syncthreads();
    }

    // epilogue: scatter to y
#pragma unroll
    for (int f = 0; f < 2; f++) {
        int r0 = m0 + wm * 32 + f * 16 + gid;
        int r1 = r0 + 8;
        int t0 = 0, s0 = 0, t1 = 0, s1 = 0;
        if (r0 < cnt) { t0 = g_tok[e * T + r0]; s0 = g_slot[e * T + r0]; }
        if (r1 < cnt) { t1 = g_tok[e * T + r1]; s1 = g_slot[e * T + r1]; }
#pragma unroll
        for (int j = 0; j < 8; j++) {
            int col = h0 + wh * 64 + j * 8 + tg * 2;
            if (r0 < cnt)
                *(float2*)(g_y + ((size_t)(t0 * TK + s0)) * HD + col)
                    = make_float2(acc[f][j][0], acc[f][j][1]);
            if (r1 < cnt)
                *(float2*)(g_y + ((size_t)(t1 * TK + s1)) * HD + col)
                    = make_float2(acc[f][j][2], acc[f][j][3]);
        }
    }
#undef G2_LOAD
}

// ---------------- combine ----------------
__global__ void combine_kernel(float* __restrict__ out) {
    int idx = blockIdx.x * blockDim.x + threadIdx.x;
    int t = idx / (HD / 4);
    int h4 = (idx % (HD / 4)) * 4;
    float4 o = make_float4(0.f, 0.f, 0.f, 0.f);
#pragma unroll
    for (int k = 0; k < TK; k++) {
        float w = g_wt[t * TK + k];
        float4 yv = *(const float4*)(g_y + ((size_t)(t * TK + k)) * HD + h4);
        o.x += w * yv.x; o.y += w * yv.y; o.z += w * yv.z; o.w += w * yv.w;
    }
    *(float4*)(out + (size_t)t * HD + h4) = o;
}

// ---------------- launcher ----------------
extern "C" void kernel_launch(void* const* d_in, const int* in_sizes, int n_in,
                              void* d_out, int out_size) {
    const float* hidden = (const float*)d_in[0];
    const float* logits = (const float*)d_in[1];
    const float* bias   = (const float*)d_in[2];
    const float* w13    = (const float*)d_in[3];
    const float* w2     = (const float*)d_in[4];
    float* out = (float*)d_out;

    const int smem_bytes = 2 * TILE_F * sizeof(float);   // 92160
    cudaFuncSetAttribute(gemm1_kernel, cudaFuncAttributeMaxDynamicSharedMemorySize, smem_bytes);
    cudaFuncSetAttribute(gemm2_kernel, cudaFuncAttributeMaxDynamicSharedMemorySize, smem_bytes);

    routing_kernel<<<1, 256>>>(logits, bias);

    dim3 g1(ID / 128, T / 64, NE);   // 6 x 4 x 32
    gemm1_kernel<<<g1, 256, smem_bytes>>>(hidden, w13);

    dim3 g2(HD / 256, T / 64, NE);   // 4 x 4 x 32
    gemm2_kernel<<<g2, 256, smem_bytes>>>(w2);

    combine_kernel<<<(T * HD / 4) / 256, 256>>>(out);
}

// round 9
// speedup vs baseline: 1.8078x; 1.6414x over previous
#include <cuda_runtime.h>
#include <cuda_bf16.h>
#include <cuda_fp16.h>
#include <math.h>
#include <stdint.h>

#define T 256
#define HD 1024
#define ID 768
#define NE 32
#define TK 6
#define NG 8
#define GSZ 4
#define KG 4

// smem: fp16 tiles, k32 per stage, row stride 40 halfs (80B: ldmatrix conflict-free)
#define RSTR 40
#define BUF_H 15360   // halfs per buffer (both gemms)

// ---------------- scratch ----------------
__device__ int    g_cnt[NE];
__device__ int    g_tok[NE * T];
__device__ int    g_slot[NE * T];
__device__ float  g_wt[T * TK];
__device__ __half g_act_hi[(size_t)NE * T * ID];
__device__ __half g_act_lo[(size_t)NE * T * ID];
__device__ float  g_y[(size_t)T * TK * HD];

// ---------------- routing (verified) ----------------
__global__ void routing_kernel(const float* __restrict__ logits,
                               const float* __restrict__ bias) {
    int tid = threadIdx.x;
    if (tid < NE) g_cnt[tid] = 0;
    __syncthreads();

    int t = tid;
    float s[NE], sc[NE];
#pragma unroll
    for (int e = 0; e < NE; e++) {
        float l = logits[t * NE + e];
        float sig = 1.0f / (1.0f + expf(-l));
        s[e] = sig;
        sc[e] = sig + bias[e];
    }
    float gs[NG];
#pragma unroll
    for (int g = 0; g < NG; g++) {
        float m1 = -3.4e38f, m2 = -3.4e38f;
#pragma unroll
        for (int j = 0; j < GSZ; j++) {
            float v = sc[g * GSZ + j];
            if (v > m1) { m2 = m1; m1 = v; }
            else if (v > m2) { m2 = v; }
        }
        gs[g] = m1 + m2;
    }
    bool gsel[NG];
#pragma unroll
    for (int g = 0; g < NG; g++) gsel[g] = false;
#pragma unroll
    for (int it = 0; it < KG; it++) {
        float best = -3.4e38f; int bi = 0;
#pragma unroll
        for (int g = 0; g < NG; g++)
            if (!gsel[g] && gs[g] > best) { best = gs[g]; bi = g; }
        gsel[bi] = true;
    }
    float msc[NE];
#pragma unroll
    for (int e = 0; e < NE; e++)
        msc[e] = gsel[e / GSZ] ? sc[e] : -3.4e38f;

    int ids[TK]; float w[TK]; float wsum = 0.0f;
#pragma unroll
    for (int k = 0; k < TK; k++) {
        float best = -3.4e38f; int bi = 0;
#pragma unroll
        for (int e = 0; e < NE; e++)
            if (msc[e] > best) { best = msc[e]; bi = e; }
        ids[k] = bi;
        msc[bi] = -3.4e38f;
        w[k] = s[bi];
        wsum += w[k];
    }
    float inv = 1.0f / wsum;
#pragma unroll
    for (int k = 0; k < TK; k++) {
        g_wt[t * TK + k] = w[k] * inv;
        int e = ids[k];
        int j = atomicAdd(&g_cnt[e], 1);
        g_tok[e * T + j]  = t;
        g_slot[e * T + j] = k;
    }
}

// ---------------- helpers ----------------
__device__ __forceinline__ void mma16(float* c, const unsigned* a, unsigned b0, unsigned b1) {
    asm volatile(
        "mma.sync.aligned.m16n8k16.row.col.f32.f16.f16.f32 "
        "{%0,%1,%2,%3}, {%4,%5,%6,%7}, {%8,%9}, {%0,%1,%2,%3};\n"
        : "+f"(c[0]), "+f"(c[1]), "+f"(c[2]), "+f"(c[3])
        : "r"(a[0]), "r"(a[1]), "r"(a[2]), "r"(a[3]), "r"(b0), "r"(b1));
}
__device__ __forceinline__ void ldsm4(unsigned* r, uint32_t a) {
    asm volatile("ldmatrix.sync.aligned.m8n8.x4.shared.b16 {%0,%1,%2,%3}, [%4];\n"
                 : "=r"(r[0]), "=r"(r[1]), "=r"(r[2]), "=r"(r[3]) : "r"(a));
}
__device__ __forceinline__ uint32_t s2u(const void* p) {
    return (uint32_t)__cvta_generic_to_shared(p);
}
// fp32 pair -> fp16 hi pair + fp16 lo pair (packed u32 each)
__device__ __forceinline__ void cvt_hilo(float x, float y, unsigned& hi, unsigned& lo) {
    __half2 h = __floats2half2_rn(x, y);
    float2 hf = __half22float2(h);
    __half2 l = __floats2half2_rn(x - hf.x, y - hf.y);
    hi = *(unsigned*)&h;
    lo = *(unsigned*)&l;
}
// store float4 as hi/lo planes at half-index (8B-aligned)
__device__ __forceinline__ void sts_hilo(__half* hb, __half* lb, float4 v) {
    unsigned h0, l0, h1, l1;
    cvt_hilo(v.x, v.y, h0, l0);
    cvt_hilo(v.z, v.w, h1, l1);
    *(uint2*)hb = make_uint2(h0, h1);
    *(uint2*)lb = make_uint2(l0, l1);
}

// ---------------- GEMM1 + SiLU ----------------
// block m64 x i64 (gate+up), 8 warps: wm=wid&1 (m32), wi=wid>>1 (i16).
// buffer layout (halfs): Ahi[64][40] Alo Bghi[64][40] Bglo Buhi Bulo
#define A_HI 0
#define A_LO 2560
#define BG_HI 5120
#define BG_LO 7680
#define BU_HI 10240
#define BU_LO 12800

__global__ __launch_bounds__(256, 2) void gemm1_kernel(const float* __restrict__ hidden,
                                                       const float* __restrict__ w13) {
    int e = blockIdx.z;
    int cnt = g_cnt[e];
    int m0 = blockIdx.y * 64;
    if (m0 >= cnt) return;
    int i0 = blockIdx.x * 64;

    extern __shared__ __align__(16) __half smh[];
    __half* bufs[2] = { smh, smh + BUF_H };

    int tid = threadIdx.x;
    int lane = tid & 31, wid = tid >> 5;
    int wm = wid & 1, wi = wid >> 1;
    int gid = lane >> 2, tg = lane & 3;

    const float* w13e = w13 + (size_t)e * 2 * ID * HD;

    // loader: row r = tid>>3 (0..31) and r+32; k quad = (tid&7)*4
    int lr = tid >> 3;
    int lk4 = (tid & 7) * 4;
    int tokA0 = (m0 + lr < cnt) ? g_tok[e * T + m0 + lr] : -1;
    int tokA1 = (m0 + lr + 32 < cnt) ? g_tok[e * T + m0 + lr + 32] : -1;

    float cg[2][2][4], cu[2][2][4];
#pragma unroll
    for (int f = 0; f < 2; f++)
#pragma unroll
        for (int n = 0; n < 2; n++)
#pragma unroll
            for (int q = 0; q < 4; q++) { cg[f][n][q] = 0.f; cu[f][n][q] = 0.f; }

    float4 sA0, sA1, sG0, sG1, sU0, sU1;
    const float4 z4 = make_float4(0.f, 0.f, 0.f, 0.f);

#define G1_LDG(k0)                                                                     \
    {                                                                                  \
        sA0 = (tokA0 >= 0) ? *(const float4*)(hidden + (size_t)tokA0 * HD + (k0) + lk4) : z4; \
        sA1 = (tokA1 >= 0) ? *(const float4*)(hidden + (size_t)tokA1 * HD + (k0) + lk4) : z4; \
        sG0 = *(const float4*)(w13e + (size_t)(i0 + lr) * HD + (k0) + lk4);            \
        sG1 = *(const float4*)(w13e + (size_t)(i0 + lr + 32) * HD + (k0) + lk4);       \
        sU0 = *(const float4*)(w13e + (size_t)(ID + i0 + lr) * HD + (k0) + lk4);       \
        sU1 = *(const float4*)(w13e + (size_t)(ID + i0 + lr + 32) * HD + (k0) + lk4);  \
    }
#define G1_STS(b_)                                                                     \
    {                                                                                  \
        sts_hilo(b_ + A_HI + lr * RSTR + lk4,        b_ + A_LO + lr * RSTR + lk4,        sA0); \
        sts_hilo(b_ + A_HI + (lr + 32) * RSTR + lk4, b_ + A_LO + (lr + 32) * RSTR + lk4, sA1); \
        sts_hilo(b_ + BG_HI + lr * RSTR + lk4,        b_ + BG_LO + lr * RSTR + lk4,        sG0); \
        sts_hilo(b_ + BG_HI + (lr + 32) * RSTR + lk4, b_ + BG_LO + (lr + 32) * RSTR + lk4, sG1); \
        sts_hilo(b_ + BU_HI + lr * RSTR + lk4,        b_ + BU_LO + lr * RSTR + lk4,        sU0); \
        sts_hilo(b_ + BU_HI + (lr + 32) * RSTR + lk4, b_ + BU_LO + (lr + 32) * RSTR + lk4, sU1); \
    }

    // ldmatrix lane addressing
    int laA = lane & 15;            // A row within m16
    int lkA = (lane >> 4) * 8;      // A k offset
    int laB = (lane & 7) + ((lane >> 4) << 3);  // B row within n16
    int lkB = ((lane >> 3) & 1) * 8;            // B k offset

    G1_LDG(0);
    G1_STS(bufs[0]);

    const int NT = HD / 32;   // 32
    for (int kt = 0; kt < NT; kt++) {
        __syncthreads();
        __half* cur = bufs[kt & 1];
        if (kt + 1 < NT) G1_LDG((kt + 1) * 32);

#pragma unroll
        for (int kk = 0; kk < 32; kk += 16) {
            unsigned Ah[2][4], Al[2][4], Bg[4], Bgl[4], Bu[4], Bul[4];
#pragma unroll
            for (int f = 0; f < 2; f++) {
                int row = wm * 32 + f * 16 + laA;
                ldsm4(Ah[f], s2u(cur + A_HI + row * RSTR + kk + lkA));
                ldsm4(Al[f], s2u(cur + A_LO + row * RSTR + kk + lkA));
            }
            int brow = wi * 16 + laB;
            ldsm4(Bg,  s2u(cur + BG_HI + brow * RSTR + kk + lkB));
            ldsm4(Bgl, s2u(cur + BG_LO + brow * RSTR + kk + lkB));
            ldsm4(Bu,  s2u(cur + BU_HI + brow * RSTR + kk + lkB));
            ldsm4(Bul, s2u(cur + BU_LO + brow * RSTR + kk + lkB));
#pragma unroll
            for (int f = 0; f < 2; f++)
#pragma unroll
                for (int nt = 0; nt < 2; nt++) {
                    mma16(cg[f][nt], Ah[f], Bg[nt * 2],  Bg[nt * 2 + 1]);
                    mma16(cg[f][nt], Al[f], Bg[nt * 2],  Bg[nt * 2 + 1]);
                    mma16(cg[f][nt], Ah[f], Bgl[nt * 2], Bgl[nt * 2 + 1]);
                    mma16(cu[f][nt], Ah[f], Bu[nt * 2],  Bu[nt * 2 + 1]);
                    mma16(cu[f][nt], Al[f], Bu[nt * 2],  Bu[nt * 2 + 1]);
                    mma16(cu[f][nt], Ah[f], Bul[nt * 2], Bul[nt * 2 + 1]);
                }
        }
        if (kt + 1 < NT) G1_STS(bufs[(kt + 1) & 1]);
    }

    // epilogue: act = silu(g)*u -> hi/lo planes
#pragma unroll
    for (int f = 0; f < 2; f++) {
        int r0 = m0 + wm * 32 + f * 16 + gid;
        int r1 = r0 + 8;
#pragma unroll
        for (int nt = 0; nt < 2; nt++) {
            int col = i0 + wi * 16 + nt * 8 + tg * 2;
            if (r0 < cnt) {
                float gA = cg[f][nt][0], gB = cg[f][nt][1];
                float uA = cu[f][nt][0], uB = cu[f][nt][1];
                float a0 = gA / (1.f + expf(-gA)) * uA;
                float a1 = gB / (1.f + expf(-gB)) * uB;
                unsigned h, l;
                cvt_hilo(a0, a1, h, l);
                size_t off = ((size_t)(e * T + r0)) * ID + col;
                *(unsigned*)(g_act_hi + off) = h;
                *(unsigned*)(g_act_lo + off) = l;
            }
            if (r1 < cnt) {
                float gA = cg[f][nt][2], gB = cg[f][nt][3];
                float uA = cu[f][nt][2], uB = cu[f][nt][3];
                float a0 = gA / (1.f + expf(-gA)) * uA;
                float a1 = gB / (1.f + expf(-gB)) * uB;
                unsigned h, l;
                cvt_hilo(a0, a1, h, l);
                size_t off = ((size_t)(e * T + r1)) * ID + col;
                *(unsigned*)(g_act_hi + off) = h;
                *(unsigned*)(g_act_lo + off) = l;
            }
        }
    }
#undef G1_LDG
#undef G1_STS
}

// ---------------- GEMM2 ----------------
// block m64 x h128, 8 warps: wm=wid&1 (m32), wh=wid>>1 (h32, 4 ntiles).
// buffer (halfs): Ahi[64][40] Alo Bhi[128][40] Blo
#define A2_HI 0
#define A2_LO 2560
#define B2_HI 5120
#define B2_LO 10240

__global__ __launch_bounds__(256, 2) void gemm2_kernel(const float* __restrict__ w2) {
    int e = blockIdx.z;
    int cnt = g_cnt[e];
    int m0 = blockIdx.y * 64;
    if (m0 >= cnt) return;
    int h0 = blockIdx.x * 128;

    extern __shared__ __align__(16) __half smh[];
    __half* bufs[2] = { smh, smh + BUF_H };

    int tid = threadIdx.x;
    int lane = tid & 31, wid = tid >> 5;
    int wm = wid & 1, wh = wid >> 1;
    int gid = lane >> 2, tg = lane & 3;

    const float* w2e = w2 + (size_t)e * HD * ID;
    const __half* ahi = g_act_hi + (size_t)e * T * ID;
    const __half* alo = g_act_lo + (size_t)e * T * ID;

    // A loader: direct fp16 copy. chunk: row = tid>>2 (0..63), koff = (tid&3)*8 halfs
    int ar = tid >> 2;
    int ak = (tid & 3) * 8;
    // B loader: row = (tid+256j)>>3 (0..127), k quad = (tid&7)*4
    int br = tid >> 3;
    int bk4 = (tid & 7) * 4;

    float acc[2][4][4];
#pragma unroll
    for (int f = 0; f < 2; f++)
#pragma unroll
        for (int n = 0; n < 4; n++)
#pragma unroll
            for (int q = 0; q < 4; q++) acc[f][n][q] = 0.f;

    uint4 sAh, sAl;
    float4 sB0, sB1, sB2, sB3;

#define G2_LDG(k0)                                                                    \
    {                                                                                 \
        sAh = *(const uint4*)(ahi + (size_t)(m0 + ar) * ID + (k0) + ak);              \
        sAl = *(const uint4*)(alo + (size_t)(m0 + ar) * ID + (k0) + ak);              \
        sB0 = *(const float4*)(w2e + (size_t)(h0 + br) * ID + (k0) + bk4);            \
        sB1 = *(const float4*)(w2e + (size_t)(h0 + br + 32) * ID + (k0) + bk4);       \
        sB2 = *(const float4*)(w2e + (size_t)(h0 + br + 64) * ID + (k0) + bk4);       \
        sB3 = *(const float4*)(w2e + (size_t)(h0 + br + 96) * ID + (k0) + bk4);       \
    }
#define G2_STS(b_)                                                                    \
    {                                                                                 \
        *(uint4*)(b_ + A2_HI + ar * RSTR + ak) = sAh;                                 \
        *(uint4*)(b_ + A2_LO + ar * RSTR + ak) = sAl;                                 \
        sts_hilo(b_ + B2_HI + br * RSTR + bk4,        b_ + B2_LO + br * RSTR + bk4,        sB0); \
        sts_hilo(b_ + B2_HI + (br + 32) * RSTR + bk4, b_ + B2_LO + (br + 32) * RSTR + bk4, sB1); \
        sts_hilo(b_ + B2_HI + (br + 64) * RSTR + bk4, b_ + B2_LO + (br + 64) * RSTR + bk4, sB2); \
        sts_hilo(b_ + B2_HI + (br + 96) * RSTR + bk4, b_ + B2_LO + (br + 96) * RSTR + bk4, sB3); \
    }

    int laA = lane & 15;
    int lkA = (lane >> 4) * 8;
    int laB = (lane & 7) + ((lane >> 4) << 3);
    int lkB = ((lane >> 3) & 1) * 8;

    G2_LDG(0);
    G2_STS(bufs[0]);

    const int NT = ID / 32;   // 24
    for (int kt = 0; kt < NT; kt++) {
        __syncthreads();
        __half* cur = bufs[kt & 1];
        if (kt + 1 < NT) G2_LDG((kt + 1) * 32);

#pragma unroll
        for (int kk = 0; kk < 32; kk += 16) {
            unsigned Ah[2][4], Al[2][4], Bh[2][4], Bl[2][4];
#pragma unroll
            for (int f = 0; f < 2; f++) {
                int row = wm * 32 + f * 16 + laA;
                ldsm4(Ah[f], s2u(cur + A2_HI + row * RSTR + kk + lkA));
                ldsm4(Al[f], s2u(cur + A2_LO + row * RSTR + kk + lkA));
            }
#pragma unroll
            for (int g = 0; g < 2; g++) {
                int row = wh * 32 + g * 16 + laB;
                ldsm4(Bh[g], s2u(cur + B2_HI + row * RSTR + kk + lkB));
                ldsm4(Bl[g], s2u(cur + B2_LO + row * RSTR + kk + lkB));
            }
#pragma unroll
            for (int f = 0; f < 2; f++)
#pragma unroll
                for (int n = 0; n < 4; n++) {
                    unsigned bh0 = Bh[n >> 1][(n & 1) * 2], bh1 = Bh[n >> 1][(n & 1) * 2 + 1];
                    unsigned bl0 = Bl[n >> 1][(n & 1) * 2], bl1 = Bl[n >> 1][(n & 1) * 2 + 1];
                    mma16(acc[f][n], Ah[f], bh0, bh1);
                    mma16(acc[f][n], Al[f], bh0, bh1);
                    mma16(acc[f][n], Ah[f], bl0, bl1);
                }
        }
        if (kt + 1 < NT) G2_STS(bufs[(kt + 1) & 1]);
    }

    // epilogue: scatter to y
#pragma unroll
    for (int f = 0; f < 2; f++) {
        int r0 = m0 + wm * 32 + f * 16 + gid;
        int r1 = r0 + 8;
        int t0 = 0, s0 = 0, t1 = 0, s1 = 0;
        if (r0 < cnt) { t0 = g_tok[e * T + r0]; s0 = g_slot[e * T + r0]; }
        if (r1 < cnt) { t1 = g_tok[e * T + r1]; s1 = g_slot[e * T + r1]; }
#pragma unroll
        for (int n = 0; n < 4; n++) {
            int col = h0 + wh * 32 + n * 8 + tg * 2;
            if (r0 < cnt)
                *(float2*)(g_y + ((size_t)(t0 * TK + s0)) * HD + col)
                    = make_float2(acc[f][n][0], acc[f][n][1]);
            if (r1 < cnt)
                *(float2*)(g_y + ((size_t)(t1 * TK + s1)) * HD + col)
                    = make_float2(acc[f][n][2], acc[f][n][3]);
        }
    }
#undef G2_LDG
#undef G2_STS
}

// ---------------- combine ----------------
__global__ void combine_kernel(float* __restrict__ out) {
    int idx = blockIdx.x * blockDim.x + threadIdx.x;
    int t = idx / (HD / 4);
    int h4 = (idx % (HD / 4)) * 4;
    float4 o = make_float4(0.f, 0.f, 0.f, 0.f);
#pragma unroll
    for (int k = 0; k < TK; k++) {
        float w = g_wt[t * TK + k];
        float4 yv = *(const float4*)(g_y + ((size_t)(t * TK + k)) * HD + h4);
        o.x += w * yv.x; o.y += w * yv.y; o.z += w * yv.z; o.w += w * yv.w;
    }
    *(float4*)(out + (size_t)t * HD + h4) = o;
}

// ---------------- launcher ----------------
extern "C" void kernel_launch(void* const* d_in, const int* in_sizes, int n_in,
                              void* d_out, int out_size) {
    const float* hidden = (const float*)d_in[0];
    const float* logits = (const float*)d_in[1];
    const float* bias   = (const float*)d_in[2];
    const float* w13    = (const float*)d_in[3];
    const float* w2     = (const float*)d_in[4];
    float* out = (float*)d_out;

    const int smem_bytes = 2 * BUF_H * sizeof(__half);   // 61440
    cudaFuncSetAttribute(gemm1_kernel, cudaFuncAttributeMaxDynamicSharedMemorySize, smem_bytes);
    cudaFuncSetAttribute(gemm2_kernel, cudaFuncAttributeMaxDynamicSharedMemorySize, smem_bytes);

    routing_kernel<<<1, 256>>>(logits, bias);

    dim3 g1(ID / 64, T / 64, NE);    // 12 x 4 x 32
    gemm1_kernel<<<g1, 256, smem_bytes>>>(hidden, w13);

    dim3 g2(HD / 128, T / 64, NE);   // 8 x 4 x 32
    gemm2_kernel<<<g2, 256, smem_bytes>>>(w2);

    combine_kernel<<<(T * HD / 4) / 256, 256>>>(out);
}

// round 10
// speedup vs baseline: 2.0850x; 1.1533x over previous
#include <cuda_runtime.h>
#include <cuda_bf16.h>
#include <cuda_fp16.h>
#include <math.h>
#include <stdint.h>

#define T 256
#define HD 1024
#define ID 768
#define NE 32
#define TK 6
#define NG 8
#define GSZ 4
#define KG 4

// smem: fp16 tiles, k32 per stage, row stride 40 halfs (80B: ldmatrix conflict-free)
#define RSTR 40
#define BUF_H 10240   // halfs per buffer (both gemms)

// ---------------- scratch ----------------
__device__ int    g_cnt[NE];
__device__ int    g_tok[NE * T];
__device__ int    g_slot[NE * T];
__device__ float  g_wt[T * TK];
__device__ __half g_act_hi[(size_t)NE * T * ID];
__device__ __half g_act_lo[(size_t)NE * T * ID];
__device__ float  g_y[(size_t)T * TK * HD];

// ---------------- routing (verified) ----------------
__global__ void routing_kernel(const float* __restrict__ logits,
                               const float* __restrict__ bias) {
    int tid = threadIdx.x;
    if (tid < NE) g_cnt[tid] = 0;
    __syncthreads();

    int t = tid;
    float s[NE], sc[NE];
#pragma unroll
    for (int e = 0; e < NE; e++) {
        float l = logits[t * NE + e];
        float sig = 1.0f / (1.0f + expf(-l));
        s[e] = sig;
        sc[e] = sig + bias[e];
    }
    float gs[NG];
#pragma unroll
    for (int g = 0; g < NG; g++) {
        float m1 = -3.4e38f, m2 = -3.4e38f;
#pragma unroll
        for (int j = 0; j < GSZ; j++) {
            float v = sc[g * GSZ + j];
            if (v > m1) { m2 = m1; m1 = v; }
            else if (v > m2) { m2 = v; }
        }
        gs[g] = m1 + m2;
    }
    bool gsel[NG];
#pragma unroll
    for (int g = 0; g < NG; g++) gsel[g] = false;
#pragma unroll
    for (int it = 0; it < KG; it++) {
        float best = -3.4e38f; int bi = 0;
#pragma unroll
        for (int g = 0; g < NG; g++)
            if (!gsel[g] && gs[g] > best) { best = gs[g]; bi = g; }
        gsel[bi] = true;
    }
    float msc[NE];
#pragma unroll
    for (int e = 0; e < NE; e++)
        msc[e] = gsel[e / GSZ] ? sc[e] : -3.4e38f;

    int ids[TK]; float w[TK]; float wsum = 0.0f;
#pragma unroll
    for (int k = 0; k < TK; k++) {
        float best = -3.4e38f; int bi = 0;
#pragma unroll
        for (int e = 0; e < NE; e++)
            if (msc[e] > best) { best = msc[e]; bi = e; }
        ids[k] = bi;
        msc[bi] = -3.4e38f;
        w[k] = s[bi];
        wsum += w[k];
    }
    float inv = 1.0f / wsum;
#pragma unroll
    for (int k = 0; k < TK; k++) {
        g_wt[t * TK + k] = w[k] * inv;
        int e = ids[k];
        int j = atomicAdd(&g_cnt[e], 1);
        g_tok[e * T + j]  = t;
        g_slot[e * T + j] = k;
    }
}

// ---------------- helpers ----------------
__device__ __forceinline__ void mma16(float* c, const unsigned* a, unsigned b0, unsigned b1) {
    asm volatile(
        "mma.sync.aligned.m16n8k16.row.col.f32.f16.f16.f32 "
        "{%0,%1,%2,%3}, {%4,%5,%6,%7}, {%8,%9}, {%0,%1,%2,%3};\n"
        : "+f"(c[0]), "+f"(c[1]), "+f"(c[2]), "+f"(c[3])
        : "r"(a[0]), "r"(a[1]), "r"(a[2]), "r"(a[3]), "r"(b0), "r"(b1));
}
__device__ __forceinline__ void ldsm4(unsigned* r, uint32_t a) {
    asm volatile("ldmatrix.sync.aligned.m8n8.x4.shared.b16 {%0,%1,%2,%3}, [%4];\n"
                 : "=r"(r[0]), "=r"(r[1]), "=r"(r[2]), "=r"(r[3]) : "r"(a));
}
__device__ __forceinline__ uint32_t s2u(const void* p) {
    return (uint32_t)__cvta_generic_to_shared(p);
}
// fp32 pair -> fp16 hi pair + fp16 lo pair (packed u32 each)
__device__ __forceinline__ void cvt_hilo(float x, float y, unsigned& hi, unsigned& lo) {
    __half2 h = __floats2half2_rn(x, y);
    float2 hf = __half22float2(h);
    __half2 l = __floats2half2_rn(x - hf.x, y - hf.y);
    hi = *(unsigned*)&h;
    lo = *(unsigned*)&l;
}
// store float4 as hi/lo planes at half-index (8B-aligned)
__device__ __forceinline__ void sts_hilo(__half* hb, __half* lb, float4 v) {
    unsigned h0, l0, h1, l1;
    cvt_hilo(v.x, v.y, h0, l0);
    cvt_hilo(v.z, v.w, h1, l1);
    *(uint2*)hb = make_uint2(h0, h1);
    *(uint2*)lb = make_uint2(l0, l1);
}
// store float4 as hi plane only (weights: single fp16 plane)
__device__ __forceinline__ void sts_hi(__half* hb, float4 v) {
    __half2 h0 = __floats2half2_rn(v.x, v.y);
    __half2 h1 = __floats2half2_rn(v.z, v.w);
    *(uint2*)hb = make_uint2(*(unsigned*)&h0, *(unsigned*)&h1);
}

// ---------------- GEMM1 + SiLU ----------------
// block m64 x i64 (gate+up), 8 warps: wm=wid&1 (m32), wi=wid>>1 (i16).
// buffer layout (halfs): Ahi[64][40] Alo[64][40] Bghi[64][40] Buhi[64][40]
#define A_HI 0
#define A_LO 2560
#define BG_HI 5120
#define BU_HI 7680

__global__ __launch_bounds__(256, 2) void gemm1_kernel(const float* __restrict__ hidden,
                                                       const float* __restrict__ w13) {
    int e = blockIdx.z;
    int cnt = g_cnt[e];
    int m0 = blockIdx.y * 64;
    if (m0 >= cnt) return;
    int i0 = blockIdx.x * 64;

    extern __shared__ __align__(16) __half smh[];
    __half* bufs[2] = { smh, smh + BUF_H };

    int tid = threadIdx.x;
    int lane = tid & 31, wid = tid >> 5;
    int wm = wid & 1, wi = wid >> 1;
    int gid = lane >> 2, tg = lane & 3;

    const float* w13e = w13 + (size_t)e * 2 * ID * HD;

    // loader: row r = tid>>3 (0..31) and r+32; k quad = (tid&7)*4
    int lr = tid >> 3;
    int lk4 = (tid & 7) * 4;
    int tokA0 = (m0 + lr < cnt) ? g_tok[e * T + m0 + lr] : -1;
    int tokA1 = (m0 + lr + 32 < cnt) ? g_tok[e * T + m0 + lr + 32] : -1;

    float cg[2][2][4], cu[2][2][4];
#pragma unroll
    for (int f = 0; f < 2; f++)
#pragma unroll
        for (int n = 0; n < 2; n++)
#pragma unroll
            for (int q = 0; q < 4; q++) { cg[f][n][q] = 0.f; cu[f][n][q] = 0.f; }

    float4 sA0, sA1, sG0, sG1, sU0, sU1;
    const float4 z4 = make_float4(0.f, 0.f, 0.f, 0.f);

#define G1_LDG(k0)                                                                     \
    {                                                                                  \
        sA0 = (tokA0 >= 0) ? *(const float4*)(hidden + (size_t)tokA0 * HD + (k0) + lk4) : z4; \
        sA1 = (tokA1 >= 0) ? *(const float4*)(hidden + (size_t)tokA1 * HD + (k0) + lk4) : z4; \
        sG0 = *(const float4*)(w13e + (size_t)(i0 + lr) * HD + (k0) + lk4);            \
        sG1 = *(const float4*)(w13e + (size_t)(i0 + lr + 32) * HD + (k0) + lk4);       \
        sU0 = *(const float4*)(w13e + (size_t)(ID + i0 + lr) * HD + (k0) + lk4);       \
        sU1 = *(const float4*)(w13e + (size_t)(ID + i0 + lr + 32) * HD + (k0) + lk4);  \
    }
#define G1_STS(b_)                                                                     \
    {                                                                                  \
        sts_hilo(b_ + A_HI + lr * RSTR + lk4,        b_ + A_LO + lr * RSTR + lk4,        sA0); \
        sts_hilo(b_ + A_HI + (lr + 32) * RSTR + lk4, b_ + A_LO + (lr + 32) * RSTR + lk4, sA1); \
        sts_hi(b_ + BG_HI + lr * RSTR + lk4,        sG0);                              \
        sts_hi(b_ + BG_HI + (lr + 32) * RSTR + lk4, sG1);                              \
        sts_hi(b_ + BU_HI + lr * RSTR + lk4,        sU0);                              \
        sts_hi(b_ + BU_HI + (lr + 32) * RSTR + lk4, sU1);                              \
    }

    // ldmatrix lane addressing
    int laA = lane & 15;            // A row within m16
    int lkA = (lane >> 4) * 8;      // A k offset
    int laB = (lane & 7) + ((lane >> 4) << 3);  // B row within n16
    int lkB = ((lane >> 3) & 1) * 8;            // B k offset

    G1_LDG(0);
    G1_STS(bufs[0]);

    const int NT = HD / 32;   // 32
    for (int kt = 0; kt < NT; kt++) {
        __syncthreads();
        __half* cur = bufs[kt & 1];
        if (kt + 1 < NT) G1_LDG((kt + 1) * 32);

#pragma unroll
        for (int kk = 0; kk < 32; kk += 16) {
            unsigned Ah[2][4], Al[2][4], Bg[4], Bu[4];
#pragma unroll
            for (int f = 0; f < 2; f++) {
                int row = wm * 32 + f * 16 + laA;
                ldsm4(Ah[f], s2u(cur + A_HI + row * RSTR + kk + lkA));
                ldsm4(Al[f], s2u(cur + A_LO + row * RSTR + kk + lkA));
            }
            int brow = wi * 16 + laB;
            ldsm4(Bg, s2u(cur + BG_HI + brow * RSTR + kk + lkB));
            ldsm4(Bu, s2u(cur + BU_HI + brow * RSTR + kk + lkB));
#pragma unroll
            for (int f = 0; f < 2; f++)
#pragma unroll
                for (int nt = 0; nt < 2; nt++) {
                    mma16(cg[f][nt], Ah[f], Bg[nt * 2], Bg[nt * 2 + 1]);
                    mma16(cg[f][nt], Al[f], Bg[nt * 2], Bg[nt * 2 + 1]);
                    mma16(cu[f][nt], Ah[f], Bu[nt * 2], Bu[nt * 2 + 1]);
                    mma16(cu[f][nt], Al[f], Bu[nt * 2], Bu[nt * 2 + 1]);
                }
        }
        if (kt + 1 < NT) G1_STS(bufs[(kt + 1) & 1]);
    }

    // epilogue: act = silu(g)*u -> hi/lo planes
#pragma unroll
    for (int f = 0; f < 2; f++) {
        int r0 = m0 + wm * 32 + f * 16 + gid;
        int r1 = r0 + 8;
#pragma unroll
        for (int nt = 0; nt < 2; nt++) {
            int col = i0 + wi * 16 + nt * 8 + tg * 2;
            if (r0 < cnt) {
                float gA = cg[f][nt][0], gB = cg[f][nt][1];
                float uA = cu[f][nt][0], uB = cu[f][nt][1];
                float a0 = gA / (1.f + expf(-gA)) * uA;
                float a1 = gB / (1.f + expf(-gB)) * uB;
                unsigned h, l;
                cvt_hilo(a0, a1, h, l);
                size_t off = ((size_t)(e * T + r0)) * ID + col;
                *(unsigned*)(g_act_hi + off) = h;
                *(unsigned*)(g_act_lo + off) = l;
            }
            if (r1 < cnt) {
                float gA = cg[f][nt][2], gB = cg[f][nt][3];
                float uA = cu[f][nt][2], uB = cu[f][nt][3];
                float a0 = gA / (1.f + expf(-gA)) * uA;
                float a1 = gB / (1.f + expf(-gB)) * uB;
                unsigned h, l;
                cvt_hilo(a0, a1, h, l);
                size_t off = ((size_t)(e * T + r1)) * ID + col;
                *(unsigned*)(g_act_hi + off) = h;
                *(unsigned*)(g_act_lo + off) = l;
            }
        }
    }
#undef G1_LDG
#undef G1_STS
}

// ---------------- GEMM2 ----------------
// block m64 x h128, 8 warps: wm=wid&1 (m32), wh=wid>>1 (h32, 4 ntiles).
// buffer (halfs): Ahi[64][40] Alo[64][40] Bhi[128][40]
#define A2_HI 0
#define A2_LO 2560
#define B2_HI 5120

__global__ __launch_bounds__(256, 2) void gemm2_kernel(const float* __restrict__ w2) {
    int e = blockIdx.z;
    int cnt = g_cnt[e];
    int m0 = blockIdx.y * 64;
    if (m0 >= cnt) return;
    int h0 = blockIdx.x * 128;

    extern __shared__ __align__(16) __half smh[];
    __half* bufs[2] = { smh, smh + BUF_H };

    int tid = threadIdx.x;
    int lane = tid & 31, wid = tid >> 5;
    int wm = wid & 1, wh = wid >> 1;
    int gid = lane >> 2, tg = lane & 3;

    const float* w2e = w2 + (size_t)e * HD * ID;
    const __half* ahi = g_act_hi + (size_t)e * T * ID;
    const __half* alo = g_act_lo + (size_t)e * T * ID;

    // A loader: direct fp16 copy. row = tid>>2 (0..63), koff = (tid&3)*8 halfs
    int ar = tid >> 2;
    int ak = (tid & 3) * 8;
    // B loader: row = tid>>3 (0..31) + 32j, k quad = (tid&7)*4
    int br = tid >> 3;
    int bk4 = (tid & 7) * 4;

    float acc[2][4][4];
#pragma unroll
    for (int f = 0; f < 2; f++)
#pragma unroll
        for (int n = 0; n < 4; n++)
#pragma unroll
            for (int q = 0; q < 4; q++) acc[f][n][q] = 0.f;

    uint4 sAh, sAl;
    float4 sB0, sB1, sB2, sB3;

#define G2_LDG(k0)                                                                    \
    {                                                                                 \
        sAh = *(const uint4*)(ahi + (size_t)(m0 + ar) * ID + (k0) + ak);              \
        sAl = *(const uint4*)(alo + (size_t)(m0 + ar) * ID + (k0) + ak);              \
        sB0 = *(const float4*)(w2e + (size_t)(h0 + br) * ID + (k0) + bk4);            \
        sB1 = *(const float4*)(w2e + (size_t)(h0 + br + 32) * ID + (k0) + bk4);       \
        sB2 = *(const float4*)(w2e + (size_t)(h0 + br + 64) * ID + (k0) + bk4);       \
        sB3 = *(const float4*)(w2e + (size_t)(h0 + br + 96) * ID + (k0) + bk4);       \
    }
#define G2_STS(b_)                                                                    \
    {                                                                                 \
        *(uint4*)(b_ + A2_HI + ar * RSTR + ak) = sAh;                                 \
        *(uint4*)(b_ + A2_LO + ar * RSTR + ak) = sAl;                                 \
        sts_hi(b_ + B2_HI + br * RSTR + bk4,        sB0);                             \
        sts_hi(b_ + B2_HI + (br + 32) * RSTR + bk4, sB1);                             \
        sts_hi(b_ + B2_HI + (br + 64) * RSTR + bk4, sB2);                             \
        sts_hi(b_ + B2_HI + (br + 96) * RSTR + bk4, sB3);                             \
    }

    int laA = lane & 15;
    int lkA = (lane >> 4) * 8;
    int laB = (lane & 7) + ((lane >> 4) << 3);
    int lkB = ((lane >> 3) & 1) * 8;

    G2_LDG(0);
    G2_STS(bufs[0]);

    const int NT = ID / 32;   // 24
    for (int kt = 0; kt < NT; kt++) {
        __syncthreads();
        __half* cur = bufs[kt & 1];
        if (kt + 1 < NT) G2_LDG((kt + 1) * 32);

#pragma unroll
        for (int kk = 0; kk < 32; kk += 16) {
            unsigned Ah[2][4], Al[2][4], Bh[2][4];
#pragma unroll
            for (int f = 0; f < 2; f++) {
                int row = wm * 32 + f * 16 + laA;
                ldsm4(Ah[f], s2u(cur + A2_HI + row * RSTR + kk + lkA));
                ldsm4(Al[f], s2u(cur + A2_LO + row * RSTR + kk + lkA));
            }
#pragma unroll
            for (int g = 0; g < 2; g++) {
                int row = wh * 32 + g * 16 + laB;
                ldsm4(Bh[g], s2u(cur + B2_HI + row * RSTR + kk + lkB));
            }
#pragma unroll
            for (int f = 0; f < 2; f++)
#pragma unroll
                for (int n = 0; n < 4; n++) {
                    unsigned bh0 = Bh[n >> 1][(n & 1) * 2], bh1 = Bh[n >> 1][(n & 1) * 2 + 1];
                    mma16(acc[f][n], Ah[f], bh0, bh1);
                    mma16(acc[f][n], Al[f], bh0, bh1);
                }
        }
        if (kt + 1 < NT) G2_STS(bufs[(kt + 1) & 1]);
    }

    // epilogue: scatter to y
#pragma unroll
    for (int f = 0; f < 2; f++) {
        int r0 = m0 + wm * 32 + f * 16 + gid;
        int r1 = r0 + 8;
        int t0 = 0, s0 = 0, t1 = 0, s1 = 0;
        if (r0 < cnt) { t0 = g_tok[e * T + r0]; s0 = g_slot[e * T + r0]; }
        if (r1 < cnt) { t1 = g_tok[e * T + r1]; s1 = g_slot[e * T + r1]; }
#pragma unroll
        for (int n = 0; n < 4; n++) {
            int col = h0 + wh * 32 + n * 8 + tg * 2;
            if (r0 < cnt)
                *(float2*)(g_y + ((size_t)(t0 * TK + s0)) * HD + col)
                    = make_float2(acc[f][n][0], acc[f][n][1]);
            if (r1 < cnt)
                *(float2*)(g_y + ((size_t)(t1 * TK + s1)) * HD + col)
                    = make_float2(acc[f][n][2], acc[f][n][3]);
        }
    }
#undef G2_LDG
#undef G2_STS
}

// ---------------- combine ----------------
__global__ void combine_kernel(float* __restrict__ out) {
    int idx = blockIdx.x * blockDim.x + threadIdx.x;
    int t = idx / (HD / 4);
    int h4 = (idx % (HD / 4)) * 4;
    float4 o = make_float4(0.f, 0.f, 0.f, 0.f);
#pragma unroll
    for (int k = 0; k < TK; k++) {
        float w = g_wt[t * TK + k];
        float4 yv = *(const float4*)(g_y + ((size_t)(t * TK + k)) * HD + h4);
        o.x += w * yv.x; o.y += w * yv.y; o.z += w * yv.z; o.w += w * yv.w;
    }
    *(float4*)(out + (size_t)t * HD + h4) = o;
}

// ---------------- launcher ----------------
extern "C" void kernel_launch(void* const* d_in, const int* in_sizes, int n_in,
                              void* d_out, int out_size) {
    const float* hidden = (const float*)d_in[0];
    const float* logits = (const float*)d_in[1];
    const float* bias   = (const float*)d_in[2];
    const float* w13    = (const float*)d_in[3];
    const float* w2     = (const float*)d_in[4];
    float* out = (float*)d_out;

    const int smem_bytes = 2 * BUF_H * sizeof(__half);   // 40960
    cudaFuncSetAttribute(gemm1_kernel, cudaFuncAttributeMaxDynamicSharedMemorySize, smem_bytes);
    cudaFuncSetAttribute(gemm2_kernel, cudaFuncAttributeMaxDynamicSharedMemorySize, smem_bytes);

    routing_kernel<<<1, 256>>>(logits, bias);

    dim3 g1(ID / 64, T / 64, NE);    // 12 x 4 x 32
    gemm1_kernel<<<g1, 256, smem_bytes>>>(hidden, w13);

    dim3 g2(HD / 128, T / 64, NE);   // 8 x 4 x 32
    gemm2_kernel<<<g2, 256, smem_bytes>>>(w2);

    combine_kernel<<<(T * HD / 4) / 256, 256>>>(out);
}

// round 14
// speedup vs baseline: 2.2635x; 1.0856x over previous
#include <cuda_runtime.h>
#include <cuda_bf16.h>
#include <cuda_fp16.h>
#include <math.h>
#include <stdint.h>

#define T 256
#define HD 1024
#define ID 768
#define NE 32
#define TK 6
#define NG 8
#define GSZ 4
#define KG 4

// smem: fp16 tiles, k32 per stage, row stride 40 halfs (80B: ldmatrix conflict-free)
#define RSTR 40
#define BUF_H 7680   // halfs per buffer (both gemms: 192 rows x 40)

// ---------------- scratch ----------------
__device__ int    g_cnt[NE];
__device__ int    g_tok[NE * T];
__device__ int    g_slot[NE * T];
__device__ float  g_wt[T * TK];
__device__ __half g_act[(size_t)NE * T * ID];   // single fp16 plane

// ---------------- zero output (graph-safe, replaces cudaMemsetAsync) ----------------
__global__ void zero_out_kernel(float* __restrict__ out) {
    int idx = blockIdx.x * blockDim.x + threadIdx.x;
    *(float4*)(out + (size_t)idx * 4) = make_float4(0.f, 0.f, 0.f, 0.f);
}

// ---------------- routing (verified) ----------------
__global__ void routing_kernel(const float* __restrict__ logits,
                               const float* __restrict__ bias) {
    int tid = threadIdx.x;
    if (tid < NE) g_cnt[tid] = 0;
    __syncthreads();

    int t = tid;
    float s[NE], sc[NE];
#pragma unroll
    for (int e = 0; e < NE; e++) {
        float l = logits[t * NE + e];
        float sig = 1.0f / (1.0f + expf(-l));
        s[e] = sig;
        sc[e] = sig + bias[e];
    }
    float gs[NG];
#pragma unroll
    for (int g = 0; g < NG; g++) {
        float m1 = -3.4e38f, m2 = -3.4e38f;
#pragma unroll
        for (int j = 0; j < GSZ; j++) {
            float v = sc[g * GSZ + j];
            if (v > m1) { m2 = m1; m1 = v; }
            else if (v > m2) { m2 = v; }
        }
        gs[g] = m1 + m2;
    }
    bool gsel[NG];
#pragma unroll
    for (int g = 0; g < NG; g++) gsel[g] = false;
#pragma unroll
    for (int it = 0; it < KG; it++) {
        float best = -3.4e38f; int bi = 0;
#pragma unroll
        for (int g = 0; g < NG; g++)
            if (!gsel[g] && gs[g] > best) { best = gs[g]; bi = g; }
        gsel[bi] = true;
    }
    float msc[NE];
#pragma unroll
    for (int e = 0; e < NE; e++)
        msc[e] = gsel[e / GSZ] ? sc[e] : -3.4e38f;

    int ids[TK]; float w[TK]; float wsum = 0.0f;
#pragma unroll
    for (int k = 0; k < TK; k++) {
        float best = -3.4e38f; int bi = 0;
#pragma unroll
        for (int e = 0; e < NE; e++)
            if (msc[e] > best) { best = msc[e]; bi = e; }
        ids[k] = bi;
        msc[bi] = -3.4e38f;
        w[k] = s[bi];
        wsum += w[k];
    }
    float inv = 1.0f / wsum;
#pragma unroll
    for (int k = 0; k < TK; k++) {
        g_wt[t * TK + k] = w[k] * inv;
        int e = ids[k];
        int j = atomicAdd(&g_cnt[e], 1);
        g_tok[e * T + j]  = t;
        g_slot[e * T + j] = k;
    }
}

// ---------------- helpers ----------------
__device__ __forceinline__ void mma16(float* c, const unsigned* a, unsigned b0, unsigned b1) {
    asm volatile(
        "mma.sync.aligned.m16n8k16.row.col.f32.f16.f16.f32 "
        "{%0,%1,%2,%3}, {%4,%5,%6,%7}, {%8,%9}, {%0,%1,%2,%3};\n"
        : "+f"(c[0]), "+f"(c[1]), "+f"(c[2]), "+f"(c[3])
        : "r"(a[0]), "r"(a[1]), "r"(a[2]), "r"(a[3]), "r"(b0), "r"(b1));
}
__device__ __forceinline__ void ldsm4(unsigned* r, uint32_t a) {
    asm volatile("ldmatrix.sync.aligned.m8n8.x4.shared.b16 {%0,%1,%2,%3}, [%4];\n"
                 : "=r"(r[0]), "=r"(r[1]), "=r"(r[2]), "=r"(r[3]) : "r"(a));
}
__device__ __forceinline__ uint32_t s2u(const void* p) {
    return (uint32_t)__cvta_generic_to_shared(p);
}
// store float4 as packed fp16 (rn) at half-pointer (8B-aligned)
__device__ __forceinline__ void sts_hi(__half* hb, float4 v) {
    __half2 h0 = __floats2half2_rn(v.x, v.y);
    __half2 h1 = __floats2half2_rn(v.z, v.w);
    *(uint2*)hb = make_uint2(*(unsigned*)&h0, *(unsigned*)&h1);
}

// ---------------- GEMM1 + SiLU ----------------
// block m64 x i128 (2 serial i64-halves), 8 warps: wm=wid&1 (m32), wi=wid>>1 (i16).
// buffer (halfs): A[64][40] Bg[64][40] Bu[64][40]
#define A_S  0
#define BG_S 2560
#define BU_S 5120

__global__ __launch_bounds__(256, 2) void gemm1_kernel(const float* __restrict__ hidden,
                                                       const float* __restrict__ w13) {
    int e = blockIdx.z;
    int cnt = g_cnt[e];
    int m0 = blockIdx.y * 64;
    if (m0 >= cnt) return;
    int i0 = blockIdx.x * 128;

    extern __shared__ __align__(16) __half smh[];
    __half* bufs[2] = { smh, smh + BUF_H };

    int tid = threadIdx.x;
    int lane = tid & 31, wid = tid >> 5;
    int wm = wid & 1, wi = wid >> 1;
    int gid = lane >> 2, tg = lane & 3;

    const float* w13e = w13 + (size_t)e * 2 * ID * HD;

    // loader: rows tid>>3 (0..31) and +32; k quad (tid&7)*4
    int lr = tid >> 3;
    int lk4 = (tid & 7) * 4;
    int tokA0 = (m0 + lr < cnt) ? g_tok[e * T + m0 + lr] : -1;
    int tokA1 = (m0 + lr + 32 < cnt) ? g_tok[e * T + m0 + lr + 32] : -1;

    // ldmatrix lane addressing
    int laA = lane & 15;
    int lkA = (lane >> 4) * 8;
    int laB = (lane & 7) + ((lane >> 4) << 3);
    int lkB = ((lane >> 3) & 1) * 8;

    float4 sA0, sA1, sG0, sG1, sU0, sU1;
    const float4 z4 = make_float4(0.f, 0.f, 0.f, 0.f);

#define G1_LDG(k0, ib)                                                                 \
    {                                                                                  \
        sA0 = (tokA0 >= 0) ? *(const float4*)(hidden + (size_t)tokA0 * HD + (k0) + lk4) : z4; \
        sA1 = (tokA1 >= 0) ? *(const float4*)(hidden + (size_t)tokA1 * HD + (k0) + lk4) : z4; \
        sG0 = *(const float4*)(w13e + (size_t)((ib) + lr) * HD + (k0) + lk4);          \
        sG1 = *(const float4*)(w13e + (size_t)((ib) + lr + 32) * HD + (k0) + lk4);     \
        sU0 = *(const float4*)(w13e + (size_t)(ID + (ib) + lr) * HD + (k0) + lk4);     \
        sU1 = *(const float4*)(w13e + (size_t)(ID + (ib) + lr + 32) * HD + (k0) + lk4);\
    }
#define G1_STS(b_)                                                                     \
    {                                                                                  \
        sts_hi(b_ + A_S  + lr * RSTR + lk4,        sA0);                               \
        sts_hi(b_ + A_S  + (lr + 32) * RSTR + lk4, sA1);                               \
        sts_hi(b_ + BG_S + lr * RSTR + lk4,        sG0);                               \
        sts_hi(b_ + BG_S + (lr + 32) * RSTR + lk4, sG1);                               \
        sts_hi(b_ + BU_S + lr * RSTR + lk4,        sU0);                               \
        sts_hi(b_ + BU_S + (lr + 32) * RSTR + lk4, sU1);                               \
    }

    for (int ih = 0; ih < 2; ih++) {
        int ib = i0 + ih * 64;

        float cg[2][2][4], cu[2][2][4];
#pragma unroll
        for (int f = 0; f < 2; f++)
#pragma unroll
            for (int n = 0; n < 2; n++)
#pragma unroll
                for (int q = 0; q < 4; q++) { cg[f][n][q] = 0.f; cu[f][n][q] = 0.f; }

        G1_LDG(0, ib);
        G1_STS(bufs[0]);

        const int NT = HD / 32;   // 32
        for (int kt = 0; kt < NT; kt++) {
            __syncthreads();
            __half* cur = bufs[kt & 1];
            if (kt + 1 < NT) G1_LDG((kt + 1) * 32, ib);

#pragma unroll
            for (int kk = 0; kk < 32; kk += 16) {
                unsigned Ah[2][4], Bg[4], Bu[4];
#pragma unroll
                for (int f = 0; f < 2; f++) {
                    int row = wm * 32 + f * 16 + laA;
                    ldsm4(Ah[f], s2u(cur + A_S + row * RSTR + kk + lkA));
                }
                int brow = wi * 16 + laB;
                ldsm4(Bg, s2u(cur + BG_S + brow * RSTR + kk + lkB));
                ldsm4(Bu, s2u(cur + BU_S + brow * RSTR + kk + lkB));
#pragma unroll
                for (int f = 0; f < 2; f++)
#pragma unroll
                    for (int nt = 0; nt < 2; nt++) {
                        mma16(cg[f][nt], Ah[f], Bg[nt * 2], Bg[nt * 2 + 1]);
                        mma16(cu[f][nt], Ah[f], Bu[nt * 2], Bu[nt * 2 + 1]);
                    }
            }
            if (kt + 1 < NT) G1_STS(bufs[(kt + 1) & 1]);
        }

        // epilogue for this i-half: act = silu(g)*u -> fp16
#pragma unroll
        for (int f = 0; f < 2; f++) {
            int r0 = m0 + wm * 32 + f * 16 + gid;
            int r1 = r0 + 8;
#pragma unroll
            for (int nt = 0; nt < 2; nt++) {
                int col = ib + wi * 16 + nt * 8 + tg * 2;
                if (r0 < cnt) {
                    float gA = cg[f][nt][0], gB = cg[f][nt][1];
                    float uA = cu[f][nt][0], uB = cu[f][nt][1];
                    __half2 h = __floats2half2_rn(gA / (1.f + expf(-gA)) * uA,
                                                  gB / (1.f + expf(-gB)) * uB);
                    *(unsigned*)(g_act + ((size_t)(e * T + r0)) * ID + col) = *(unsigned*)&h;
                }
                if (r1 < cnt) {
                    float gA = cg[f][nt][2], gB = cg[f][nt][3];
                    float uA = cu[f][nt][2], uB = cu[f][nt][3];
                    __half2 h = __floats2half2_rn(gA / (1.f + expf(-gA)) * uA,
                                                  gB / (1.f + expf(-gB)) * uB);
                    *(unsigned*)(g_act + ((size_t)(e * T + r1)) * ID + col) = *(unsigned*)&h;
                }
            }
        }
        // next half writes buf0 first; hazard-free (readers of buf1 passed their
        // reads before the kt=0 __syncthreads of the next half)
    }
#undef G1_LDG
#undef G1_STS
}

// ---------------- GEMM2 + fused combine ----------------
// block m64 x h128, 8 warps: wm=wid&1 (m32), wh=wid>>1 (h32).
// buffer (halfs): A[64][40] B[128][40]
#define A2_S 0
#define B2_S 2560

__global__ __launch_bounds__(256, 2) void gemm2_kernel(const float* __restrict__ w2,
                                                       float* __restrict__ out) {
    int e = blockIdx.z;
    int cnt = g_cnt[e];
    int m0 = blockIdx.y * 64;
    if (m0 >= cnt) return;
    int h0 = blockIdx.x * 128;

    extern __shared__ __align__(16) __half smh[];
    __half* bufs[2] = { smh, smh + BUF_H };

    int tid = threadIdx.x;
    int lane = tid & 31, wid = tid >> 5;
    int wm = wid & 1, wh = wid >> 1;
    int gid = lane >> 2, tg = lane & 3;

    const float* w2e = w2 + (size_t)e * HD * ID;
    const __half* acte = g_act + (size_t)e * T * ID;

    // A loader: fp16 copy. row = tid>>2 (0..63), koff = (tid&3)*8 halfs
    int ar = tid >> 2;
    int ak = (tid & 3) * 8;
    // B loader: row = tid>>3 (0..31) + 32j, k quad (tid&7)*4
    int br = tid >> 3;
    int bk4 = (tid & 7) * 4;

    float acc[2][4][4];
#pragma unroll
    for (int f = 0; f < 2; f++)
#pragma unroll
        for (int n = 0; n < 4; n++)
#pragma unroll
            for (int q = 0; q < 4; q++) acc[f][n][q] = 0.f;

    uint4 sAh;
    float4 sB0, sB1, sB2, sB3;

#define G2_LDG(k0)                                                                    \
    {                                                                                 \
        sAh = *(const uint4*)(acte + (size_t)(m0 + ar) * ID + (k0) + ak);             \
        sB0 = *(const float4*)(w2e + (size_t)(h0 + br) * ID + (k0) + bk4);            \
        sB1 = *(const float4*)(w2e + (size_t)(h0 + br + 32) * ID + (k0) + bk4);       \
        sB2 = *(const float4*)(w2e + (size_t)(h0 + br + 64) * ID + (k0) + bk4);       \
        sB3 = *(const float4*)(w2e + (size_t)(h0 + br + 96) * ID + (k0) + bk4);       \
    }
#define G2_STS(b_)                                                                    \
    {                                                                                 \
        *(uint4*)(b_ + A2_S + ar * RSTR + ak) = sAh;                                  \
        sts_hi(b_ + B2_S + br * RSTR + bk4,        sB0);                              \
        sts_hi(b_ + B2_S + (br + 32) * RSTR + bk4, sB1);                              \
        sts_hi(b_ + B2_S + (br + 64) * RSTR + bk4, sB2);                              \
        sts_hi(b_ + B2_S + (br + 96) * RSTR + bk4, sB3);                              \
    }

    int laA = lane & 15;
    int lkA = (lane >> 4) * 8;
    int laB = (lane & 7) + ((lane >> 4) << 3);
    int lkB = ((lane >> 3) & 1) * 8;

    G2_LDG(0);
    G2_STS(bufs[0]);

    const int NT = ID / 32;   // 24
    for (int kt = 0; kt < NT; kt++) {
        __syncthreads();
        __half* cur = bufs[kt & 1];
        if (kt + 1 < NT) G2_LDG((kt + 1) * 32);

#pragma unroll
        for (int kk = 0; kk < 32; kk += 16) {
            unsigned Ah[2][4], Bh[2][4];
#pragma unroll
            for (int f = 0; f < 2; f++) {
                int row = wm * 32 + f * 16 + laA;
                ldsm4(Ah[f], s2u(cur + A2_S + row * RSTR + kk + lkA));
            }
#pragma unroll
            for (int g = 0; g < 2; g++) {
                int row = wh * 32 + g * 16 + laB;
                ldsm4(Bh[g], s2u(cur + B2_S + row * RSTR + kk + lkB));
            }
#pragma unroll
            for (int f = 0; f < 2; f++)
#pragma unroll
                for (int n = 0; n < 4; n++)
                    mma16(acc[f][n], Ah[f],
                          Bh[n >> 1][(n & 1) * 2], Bh[n >> 1][(n & 1) * 2 + 1]);
        }
        if (kt + 1 < NT) G2_STS(bufs[(kt + 1) & 1]);
    }

    // epilogue: fused weighted combine via atomics (out pre-zeroed)
#pragma unroll
    for (int f = 0; f < 2; f++) {
        int r0 = m0 + wm * 32 + f * 16 + gid;
        int r1 = r0 + 8;
        float w0 = 0.f, w1 = 0.f;
        int t0 = 0, t1 = 0;
        if (r0 < cnt) { t0 = g_tok[e * T + r0]; w0 = g_wt[t0 * TK + g_slot[e * T + r0]]; }
        if (r1 < cnt) { t1 = g_tok[e * T + r1]; w1 = g_wt[t1 * TK + g_slot[e * T + r1]]; }
#pragma unroll
        for (int n = 0; n < 4; n++) {
            int col = h0 + wh * 32 + n * 8 + tg * 2;
            if (r0 < cnt) {
                atomicAdd(out + (size_t)t0 * HD + col,     w0 * acc[f][n][0]);
                atomicAdd(out + (size_t)t0 * HD + col + 1, w0 * acc[f][n][1]);
            }
            if (r1 < cnt) {
                atomicAdd(out + (size_t)t1 * HD + col,     w1 * acc[f][n][2]);
                atomicAdd(out + (size_t)t1 * HD + col + 1, w1 * acc[f][n][3]);
            }
        }
    }
#undef G2_LDG
#undef G2_STS
}

// ---------------- launcher ----------------
extern "C" void kernel_launch(void* const* d_in, const int* in_sizes, int n_in,
                              void* d_out, int out_size) {
    const float* hidden = (const float*)d_in[0];
    const float* logits = (const float*)d_in[1];
    const float* bias   = (const float*)d_in[2];
    const float* w13    = (const float*)d_in[3];
    const float* w2     = (const float*)d_in[4];
    float* out = (float*)d_out;

    const int smem_bytes = 2 * BUF_H * sizeof(__half);   // 30720
    cudaFuncSetAttribute(gemm1_kernel, cudaFuncAttributeMaxDynamicSharedMemorySize, smem_bytes);
    cudaFuncSetAttribute(gemm2_kernel, cudaFuncAttributeMaxDynamicSharedMemorySize, smem_bytes);

    zero_out_kernel<<<(T * HD / 4) / 256, 256>>>(out);

    routing_kernel<<<1, 256>>>(logits, bias);

    dim3 g1(ID / 128, T / 64, NE);   // 6 x 4 x 32
    gemm1_kernel<<<g1, 256, smem_bytes>>>(hidden, w13);

    dim3 g2(HD / 128, T / 64, NE);   // 8 x 4 x 32
    gemm2_kernel<<<g2, 256, smem_bytes>>>(w2, out);
}

// round 17
// speedup vs baseline: 2.5744x; 1.1373x over previous
#include <cuda_runtime.h>
#include <cuda_bf16.h>
#include <cuda_fp16.h>
#include <math.h>
#include <stdint.h>

#define T 256
#define HD 1024
#define ID 768
#define NE 32
#define TK 6
#define NG 8
#define GSZ 4
#define KG 4

// f32 smem row stride: 40 floats (stride mod 32 = 8 -> conflict-free LDS.64 frags)
#define RSF 40
// f16 smem row stride (gemm2 A): 40 halfs (80B, ldsm conflict-free; as validated)
#define RSH 40

// gemm1 stage: A[64][40] + Bg[64][40] + Bu[64][40] f32 = 7680 f32 = 30720 B
#define G1_STAGE_F 7680
// gemm2 stage: A 64x40 halfs (5120B) + B 128x40 f32 (20480B) = 25600 B
#define G2_STAGE_B 25600

// ---------------- scratch ----------------
__device__ int    g_cnt[NE];
__device__ int    g_tok[NE * T];
__device__ int    g_slot[NE * T];
__device__ float  g_wt[T * TK];
__device__ __half g_act[(size_t)NE * T * ID];

// ---------------- zero output ----------------
__global__ void zero_out_kernel(float* __restrict__ out) {
    int idx = blockIdx.x * blockDim.x + threadIdx.x;
    *(float4*)(out + (size_t)idx * 4) = make_float4(0.f, 0.f, 0.f, 0.f);
}

// ---------------- routing (verified) ----------------
__global__ void routing_kernel(const float* __restrict__ logits,
                               const float* __restrict__ bias) {
    int tid = threadIdx.x;
    if (tid < NE) g_cnt[tid] = 0;
    __syncthreads();

    int t = tid;
    float s[NE], sc[NE];
#pragma unroll
    for (int e = 0; e < NE; e++) {
        float l = logits[t * NE + e];
        float sig = 1.0f / (1.0f + expf(-l));
        s[e] = sig;
        sc[e] = sig + bias[e];
    }
    float gs[NG];
#pragma unroll
    for (int g = 0; g < NG; g++) {
        float m1 = -3.4e38f, m2 = -3.4e38f;
#pragma unroll
        for (int j = 0; j < GSZ; j++) {
            float v = sc[g * GSZ + j];
            if (v > m1) { m2 = m1; m1 = v; }
            else if (v > m2) { m2 = v; }
        }
        gs[g] = m1 + m2;
    }
    bool gsel[NG];
#pragma unroll
    for (int g = 0; g < NG; g++) gsel[g] = false;
#pragma unroll
    for (int it = 0; it < KG; it++) {
        float best = -3.4e38f; int bi = 0;
#pragma unroll
        for (int g = 0; g < NG; g++)
            if (!gsel[g] && gs[g] > best) { best = gs[g]; bi = g; }
        gsel[bi] = true;
    }
    float msc[NE];
#pragma unroll
    for (int e = 0; e < NE; e++)
        msc[e] = gsel[e / GSZ] ? sc[e] : -3.4e38f;

    int ids[TK]; float w[TK]; float wsum = 0.0f;
#pragma unroll
    for (int k = 0; k < TK; k++) {
        float best = -3.4e38f; int bi = 0;
#pragma unroll
        for (int e = 0; e < NE; e++)
            if (msc[e] > best) { best = msc[e]; bi = e; }
        ids[k] = bi;
        msc[bi] = -3.4e38f;
        w[k] = s[bi];
        wsum += w[k];
    }
    float inv = 1.0f / wsum;
#pragma unroll
    for (int k = 0; k < TK; k++) {
        g_wt[t * TK + k] = w[k] * inv;
        int e = ids[k];
        int j = atomicAdd(&g_cnt[e], 1);
        g_tok[e * T + j]  = t;
        g_slot[e * T + j] = k;
    }
}

// ---------------- helpers ----------------
__device__ __forceinline__ void mma16(float* c, const unsigned* a, unsigned b0, unsigned b1) {
    asm volatile(
        "mma.sync.aligned.m16n8k16.row.col.f32.f16.f16.f32 "
        "{%0,%1,%2,%3}, {%4,%5,%6,%7}, {%8,%9}, {%0,%1,%2,%3};\n"
        : "+f"(c[0]), "+f"(c[1]), "+f"(c[2]), "+f"(c[3])
        : "r"(a[0]), "r"(a[1]), "r"(a[2]), "r"(a[3]), "r"(b0), "r"(b1));
}
__device__ __forceinline__ void ldsm4(unsigned* r, uint32_t a) {
    asm volatile("ldmatrix.sync.aligned.m8n8.x4.shared.b16 {%0,%1,%2,%3}, [%4];\n"
                 : "=r"(r[0]), "=r"(r[1]), "=r"(r[2]), "=r"(r[3]) : "r"(a));
}
__device__ __forceinline__ uint32_t s2u(const void* p) {
    return (uint32_t)__cvta_generic_to_shared(p);
}
__device__ __forceinline__ void cpa16(uint32_t dst, const void* src, int sz) {
    asm volatile("cp.async.cg.shared.global [%0], [%1], 16, %2;\n"
                 :: "r"(dst), "l"(src), "r"(sz));
}
__device__ __forceinline__ void cpa_commit() { asm volatile("cp.async.commit_group;\n"); }
__device__ __forceinline__ void cpa_wait1() { asm volatile("cp.async.wait_group 1;\n"); }
__device__ __forceinline__ void cpa_wait0() { asm volatile("cp.async.wait_group 0;\n"); }
// float2 -> packed half2 (rn) as u32
__device__ __forceinline__ unsigned f2h2(float2 v) {
    __half2 h = __floats2half2_rn(v.x, v.y);
    return *(unsigned*)&h;
}

// ---------------- GEMM1 + SiLU ----------------
// block m64 x i128 (2 serial i64-halves), 8 warps: wm=wid&1 (m32), wi=wid>>1 (i16).
// 3-stage cp.async pipeline; fp32 smem; fragment LDS.64 + cvt in consumer.
__global__ __launch_bounds__(256, 2) void gemm1_kernel(const float* __restrict__ hidden,
                                                       const float* __restrict__ w13) {
    int e = blockIdx.z;
    int cnt = g_cnt[e];
    int m0 = blockIdx.y * 64;
    if (m0 >= cnt) return;
    int i0 = blockIdx.x * 128;

    extern __shared__ __align__(16) float smf[];

    int tid = threadIdx.x;
    int lane = tid & 31, wid = tid >> 5;
    int wm = wid & 1, wi = wid >> 1;
    int gid = lane >> 2, tg = lane & 3;
    int cs = tg * 2;   // fragment k column pair

    const float* w13e = w13 + (size_t)e * 2 * ID * HD;

    int lr = tid >> 3;          // loader row 0..31 (and +32)
    int lk = (tid & 7) * 4;     // loader k offset (f32)
    int tokA0 = (m0 + lr < cnt) ? g_tok[e * T + m0 + lr] : -1;
    int tokA1 = (m0 + lr + 32 < cnt) ? g_tok[e * T + m0 + lr + 32] : -1;
    const float* srcA0 = hidden + (size_t)(tokA0 < 0 ? 0 : tokA0) * HD + lk;
    const float* srcA1 = hidden + (size_t)(tokA1 < 0 ? 0 : tokA1) * HD + lk;
    int szA0 = tokA0 >= 0 ? 16 : 0;
    int szA1 = tokA1 >= 0 ? 16 : 0;

#define G1_ISSUE(s3, k0, ib)                                                          \
    {                                                                                 \
        float* st_ = smf + (s3) * G1_STAGE_F;                                         \
        cpa16(s2u(st_ + lr * RSF + lk),        srcA0 + (k0), szA0);                   \
        cpa16(s2u(st_ + (lr + 32) * RSF + lk), srcA1 + (k0), szA1);                   \
        cpa16(s2u(st_ + 2560 + lr * RSF + lk),                                        \
              w13e + (size_t)((ib) + lr) * HD + (k0) + lk, 16);                       \
        cpa16(s2u(st_ + 2560 + (lr + 32) * RSF + lk),                                 \
              w13e + (size_t)((ib) + lr + 32) * HD + (k0) + lk, 16);                  \
        cpa16(s2u(st_ + 5120 + lr * RSF + lk),                                        \
              w13e + (size_t)(ID + (ib) + lr) * HD + (k0) + lk, 16);                  \
        cpa16(s2u(st_ + 5120 + (lr + 32) * RSF + lk),                                 \
              w13e + (size_t)(ID + (ib) + lr + 32) * HD + (k0) + lk, 16);             \
        cpa_commit();                                                                 \
    }

    for (int ih = 0; ih < 2; ih++) {
        int ib = i0 + ih * 64;
        if (ih) __syncthreads();   // prior half's readers done before buffer reuse

        float cg[2][2][4], cu[2][2][4];
#pragma unroll
        for (int f = 0; f < 2; f++)
#pragma unroll
            for (int n = 0; n < 2; n++)
#pragma unroll
                for (int q = 0; q < 4; q++) { cg[f][n][q] = 0.f; cu[f][n][q] = 0.f; }

        G1_ISSUE(0, 0, ib);
        G1_ISSUE(1, 32, ib);

        const int NT = HD / 32;   // 32
        for (int kt = 0; kt < NT; kt++) {
            if (kt < NT - 1) cpa_wait1(); else cpa_wait0();
            __syncthreads();
            if (kt + 2 < NT) G1_ISSUE((kt + 2) % 3, (kt + 2) * 32, ib);

            const float* st = smf + (kt % 3) * G1_STAGE_F;
#pragma unroll
            for (int kk = 0; kk < 32; kk += 16) {
                unsigned a[2][4];
#pragma unroll
                for (int f = 0; f < 2; f++) {
                    const float* ab = st + (size_t)(wm * 32 + f * 16 + gid) * RSF + kk + cs;
                    a[f][0] = f2h2(*(const float2*)(ab));
                    a[f][1] = f2h2(*(const float2*)(ab + 8 * RSF));
                    a[f][2] = f2h2(*(const float2*)(ab + 8));
                    a[f][3] = f2h2(*(const float2*)(ab + 8 * RSF + 8));
                }
#pragma unroll
                for (int nt = 0; nt < 2; nt++) {
                    const float* gb = st + 2560 + (size_t)(wi * 16 + nt * 8 + gid) * RSF + kk + cs;
                    unsigned bg0 = f2h2(*(const float2*)(gb));
                    unsigned bg1 = f2h2(*(const float2*)(gb + 8));
                    const float* ub = st + 5120 + (size_t)(wi * 16 + nt * 8 + gid) * RSF + kk + cs;
                    unsigned bu0 = f2h2(*(const float2*)(ub));
                    unsigned bu1 = f2h2(*(const float2*)(ub + 8));
#pragma unroll
                    for (int f = 0; f < 2; f++) {
                        mma16(cg[f][nt], a[f], bg0, bg1);
                        mma16(cu[f][nt], a[f], bu0, bu1);
                    }
                }
            }
        }

        // epilogue: act = silu(g)*u -> fp16
#pragma unroll
        for (int f = 0; f < 2; f++) {
            int r0 = m0 + wm * 32 + f * 16 + gid;
            int r1 = r0 + 8;
#pragma unroll
            for (int nt = 0; nt < 2; nt++) {
                int col = ib + wi * 16 + nt * 8 + tg * 2;
                if (r0 < cnt) {
                    float gA = cg[f][nt][0], gB = cg[f][nt][1];
                    float uA = cu[f][nt][0], uB = cu[f][nt][1];
                    __half2 h = __floats2half2_rn(gA / (1.f + expf(-gA)) * uA,
                                                  gB / (1.f + expf(-gB)) * uB);
                    *(unsigned*)(g_act + ((size_t)(e * T + r0)) * ID + col) = *(unsigned*)&h;
                }
                if (r1 < cnt) {
                    float gA = cg[f][nt][2], gB = cg[f][nt][3];
                    float uA = cu[f][nt][2], uB = cu[f][nt][3];
                    __half2 h = __floats2half2_rn(gA / (1.f + expf(-gA)) * uA,
                                                  gB / (1.f + expf(-gB)) * uB);
                    *(unsigned*)(g_act + ((size_t)(e * T + r1)) * ID + col) = *(unsigned*)&h;
                }
            }
        }
    }
#undef G1_ISSUE
}

// ---------------- GEMM2 + fused combine ----------------
// block m64 x h128, 8 warps: wm=wid&1 (m32), wh=wid>>1 (h32).
// 3-stage cp.async: A fp16 direct (ldsm), B fp32 (fragment LDS.64 + cvt).
__global__ __launch_bounds__(256, 2) void gemm2_kernel(const float* __restrict__ w2,
                                                       float* __restrict__ out) {
    int e = blockIdx.z;
    int cnt = g_cnt[e];
    int m0 = blockIdx.y * 64;
    if (m0 >= cnt) return;
    int h0 = blockIdx.x * 128;

    extern __shared__ __align__(16) char smc[];

    int tid = threadIdx.x;
    int lane = tid & 31, wid = tid >> 5;
    int wm = wid & 1, wh = wid >> 1;
    int gid = lane >> 2, tg = lane & 3;
    int cs = tg * 2;

    const float* w2e = w2 + (size_t)e * HD * ID;
    const __half* acte = g_act + (size_t)e * T * ID;

    // A loader: row = tid>>2 (0..63), koff = (tid&3)*8 halfs
    int ar = tid >> 2;
    int ak = (tid & 3) * 8;
    // B loader: 4 chunks: c = tid + 256j; row = c>>3 (0..127), koff = (c&7)*4 f32
    int br = tid >> 3;
    int bk = (tid & 7) * 4;

    // ldmatrix lane addressing for A
    int laA = lane & 15;
    int lkA = (lane >> 4) * 8;

    float acc[2][4][4];
#pragma unroll
    for (int f = 0; f < 2; f++)
#pragma unroll
        for (int n = 0; n < 4; n++)
#pragma unroll
            for (int q = 0; q < 4; q++) acc[f][n][q] = 0.f;

#define G2_ISSUE(s3, k0)                                                              \
    {                                                                                 \
        __half* sA_ = (__half*)(smc + (s3) * G2_STAGE_B);                             \
        float*  sB_ = (float*)(smc + (s3) * G2_STAGE_B + 5120);                       \
        cpa16(s2u(sA_ + ar * RSH + ak), acte + (size_t)(m0 + ar) * ID + (k0) + ak, 16); \
        _Pragma("unroll")                                                             \
        for (int j_ = 0; j_ < 4; j_++) {                                              \
            int row_ = br + 32 * j_;                                                  \
            cpa16(s2u(sB_ + row_ * RSF + bk),                                         \
                  w2e + (size_t)(h0 + row_) * ID + (k0) + bk, 16);                    \
        }                                                                             \
        cpa_commit();                                                                 \
    }

    G2_ISSUE(0, 0);
    G2_ISSUE(1, 32);

    const int NT = ID / 32;   // 24
    for (int kt = 0; kt < NT; kt++) {
        if (kt < NT - 1) cpa_wait1(); else cpa_wait0();
        __syncthreads();
        if (kt + 2 < NT) G2_ISSUE((kt + 2) % 3, (kt + 2) * 32);

        const __half* sA = (const __half*)(smc + (kt % 3) * G2_STAGE_B);
        const float*  sB = (const float*)(smc + (kt % 3) * G2_STAGE_B + 5120);
#pragma unroll
        for (int kk = 0; kk < 32; kk += 16) {
            unsigned Ah[2][4];
#pragma unroll
            for (int f = 0; f < 2; f++) {
                int row = wm * 32 + f * 16 + laA;
                ldsm4(Ah[f], s2u(sA + row * RSH + kk + lkA));
            }
#pragma unroll
            for (int n = 0; n < 4; n++) {
                const float* bb = sB + (size_t)(wh * 32 + n * 8 + gid) * RSF + kk + cs;
                unsigned b0 = f2h2(*(const float2*)(bb));
                unsigned b1 = f2h2(*(const float2*)(bb + 8));
#pragma unroll
                for (int f = 0; f < 2; f++)
                    mma16(acc[f][n], Ah[f], b0, b1);
            }
        }
    }

    // epilogue: fused weighted combine via atomics (out pre-zeroed)
#pragma unroll
    for (int f = 0; f < 2; f++) {
        int r0 = m0 + wm * 32 + f * 16 + gid;
        int r1 = r0 + 8;
        float w0 = 0.f, w1 = 0.f;
        int t0 = 0, t1 = 0;
        if (r0 < cnt) { t0 = g_tok[e * T + r0]; w0 = g_wt[t0 * TK + g_slot[e * T + r0]]; }
        if (r1 < cnt) { t1 = g_tok[e * T + r1]; w1 = g_wt[t1 * TK + g_slot[e * T + r1]]; }
#pragma unroll
        for (int n = 0; n < 4; n++) {
            int col = h0 + wh * 32 + n * 8 + tg * 2;
            if (r0 < cnt) {
                atomicAdd(out + (size_t)t0 * HD + col,     w0 * acc[f][n][0]);
                atomicAdd(out + (size_t)t0 * HD + col + 1, w0 * acc[f][n][1]);
            }
            if (r1 < cnt) {
                atomicAdd(out + (size_t)t1 * HD + col,     w1 * acc[f][n][2]);
                atomicAdd(out + (size_t)t1 * HD + col + 1, w1 * acc[f][n][3]);
            }
        }
    }
#undef G2_ISSUE
}

// ---------------- launcher ----------------
extern "C" void kernel_launch(void* const* d_in, const int* in_sizes, int n_in,
                              void* d_out, int out_size) {
    const float* hidden = (const float*)d_in[0];
    const float* logits = (const float*)d_in[1];
    const float* bias   = (const float*)d_in[2];
    const float* w13    = (const float*)d_in[3];
    const float* w2     = (const float*)d_in[4];
    float* out = (float*)d_out;

    const int smem1 = 3 * G1_STAGE_F * sizeof(float);   // 92160
    const int smem2 = 3 * G2_STAGE_B;                   // 76800
    cudaFuncSetAttribute(gemm1_kernel, cudaFuncAttributeMaxDynamicSharedMemorySize, smem1);
    cudaFuncSetAttribute(gemm2_kernel, cudaFuncAttributeMaxDynamicSharedMemorySize, smem2);

    zero_out_kernel<<<(T * HD / 4) / 256, 256>>>(out);

    routing_kernel<<<1, 256>>>(logits, bias);

    dim3 g1(ID / 128, T / 64, NE);   // 6 x 4 x 32
    gemm1_kernel<<<g1, 256, smem1>>>(hidden, w13);

    dim3 g2(HD / 128, T / 64, NE);   // 8 x 4 x 32
    gemm2_kernel<<<g2, 256, smem2>>>(w2, out);
}